// round 11
// baseline (speedup 1.0000x reference)
#include <cuda_runtime.h>
#include <math.h>

#define BB 8
#define NMAX 2048
#define HD 128
#define NHEADS 4
#define NLAYERS 3
#define KNN 8
#define MAXNODES (BB*NMAX)
#define LN_EPS 1e-5f

// ---------------- device scratch ----------------
__device__ __align__(256) float d_X [MAXNODES*HD];      // ping
__device__ __align__(256) float d_XG[MAXNODES*HD];      // pong
__device__ __align__(256) float d_XM[MAXNODES*2*HD];    // [XN | Mg] concat, stride 256
__device__ __align__(256) float d_XN[MAXNODES*HD];      // ln2 output
__device__ __align__(256) float d_T1[MAXNODES*HD];
__device__ __align__(256) float d_H [MAXNODES*NHEADS*HD];
__device__ __align__(256) float d_C [MAXNODES*2];
__device__ __align__(256) float d_CG[MAXNODES*2];
__device__ __align__(256) float d_WCAT[NLAYERS*256*512];
__device__ __align__(256) float d_BSCAT[NLAYERS*512];
__device__ unsigned long long d_ADJ[(size_t)MAXNODES*(NMAX/64)];
__device__ float d_DINV[MAXNODES];
__device__ float d_RDEG[MAXNODES];
__device__ float d_Y  [MAXNODES];
__device__ int   d_TOPI[BB*(NMAX/2)];
__device__ float d_TOPV[BB*(NMAX/2)];
__device__ float d_PICKS[BB*2*HD];

// ---------------- f32x2 helpers ----------------
__device__ __forceinline__ unsigned long long ffma2(unsigned long long a,
                                                    unsigned long long b,
                                                    unsigned long long c) {
    unsigned long long d;
    asm("fma.rn.f32x2 %0, %1, %2, %3;" : "=l"(d) : "l"(a), "l"(b), "l"(c));
    return d;
}
__device__ __forceinline__ unsigned long long dup2(float a) {
    unsigned long long d; unsigned int u = __float_as_uint(a);
    asm("mov.b64 %0, {%1, %1};" : "=l"(d) : "r"(u));
    return d;
}
__device__ __forceinline__ void unpack2(unsigned long long v, float& lo, float& hi) {
    unsigned int l, h;
    asm("mov.b64 {%0, %1}, %2;" : "=r"(l), "=r"(h) : "l"(v));
    lo = __uint_as_float(l); hi = __uint_as_float(h);
}

// ---------------- 128x128 tiled fp32 GEMM (R2-proven) ----------------
template<bool RELU, bool HAS_RESID, bool HAS_BN>
__global__ __launch_bounds__(256, 2)
void gemm128(const float* __restrict__ A, const float* __restrict__ Bm,
             const float* __restrict__ bias,
             const float* __restrict__ scale, const float* __restrict__ shift,
             const float* __restrict__ resid, float* __restrict__ Cout,
             int lda, int ldb, int ldc, int Kd)
{
    __shared__ float As[16][128];
    __shared__ float Bs[16][128];
    const int tid = threadIdx.x;
    const int tx = tid & 15, ty = tid >> 4;
    const int row0 = blockIdx.x * 128, col0 = blockIdx.y * 128;

    const int f0 = tid * 2, f1 = tid * 2 + 1;
    const int ar0 = f0 >> 2, ak0 = (f0 & 3) * 4;
    const int ar1 = f1 >> 2, ak1 = (f1 & 3) * 4;
    const int bk0 = f0 >> 5, bc0 = (f0 & 31) * 4;
    const int bk1 = f1 >> 5, bc1 = (f1 & 31) * 4;

    const float* Ar0 = A + (size_t)(row0 + ar0) * lda;
    const float* Ar1 = A + (size_t)(row0 + ar1) * lda;
    const float* Bp  = Bm + col0;

    unsigned long long acc[8][4];
#pragma unroll
    for (int i = 0; i < 8; i++)
#pragma unroll
        for (int j = 0; j < 4; j++) acc[i][j] = 0ull;

    float4 pa0 = *(const float4*)(Ar0 + ak0);
    float4 pa1 = *(const float4*)(Ar1 + ak1);
    float4 pb0 = *(const float4*)(Bp + (size_t)bk0 * ldb + bc0);
    float4 pb1 = *(const float4*)(Bp + (size_t)bk1 * ldb + bc1);

    for (int k0 = 0; k0 < Kd; k0 += 16) {
        As[ak0+0][ar0] = pa0.x; As[ak0+1][ar0] = pa0.y;
        As[ak0+2][ar0] = pa0.z; As[ak0+3][ar0] = pa0.w;
        As[ak1+0][ar1] = pa1.x; As[ak1+1][ar1] = pa1.y;
        As[ak1+2][ar1] = pa1.z; As[ak1+3][ar1] = pa1.w;
        *(float4*)&Bs[bk0][bc0] = pb0;
        *(float4*)&Bs[bk1][bc1] = pb1;
        __syncthreads();
        if (k0 + 16 < Kd) {
            pa0 = *(const float4*)(Ar0 + k0 + 16 + ak0);
            pa1 = *(const float4*)(Ar1 + k0 + 16 + ak1);
            pb0 = *(const float4*)(Bp + (size_t)(k0 + 16 + bk0) * ldb + bc0);
            pb1 = *(const float4*)(Bp + (size_t)(k0 + 16 + bk1) * ldb + bc1);
        }
#pragma unroll
        for (int kk = 0; kk < 16; kk++) {
            float4 a0 = *(const float4*)&As[kk][ty*8];
            float4 a1 = *(const float4*)&As[kk][ty*8+4];
            unsigned long long b2[4];
#pragma unroll
            for (int j = 0; j < 4; j++)
                b2[j] = *(const unsigned long long*)&Bs[kk][tx*8 + 2*j];
            unsigned long long a2;
            a2 = dup2(a0.x);
#pragma unroll
            for (int j = 0; j < 4; j++) acc[0][j] = ffma2(a2, b2[j], acc[0][j]);
            a2 = dup2(a0.y);
#pragma unroll
            for (int j = 0; j < 4; j++) acc[1][j] = ffma2(a2, b2[j], acc[1][j]);
            a2 = dup2(a0.z);
#pragma unroll
            for (int j = 0; j < 4; j++) acc[2][j] = ffma2(a2, b2[j], acc[2][j]);
            a2 = dup2(a0.w);
#pragma unroll
            for (int j = 0; j < 4; j++) acc[3][j] = ffma2(a2, b2[j], acc[3][j]);
            a2 = dup2(a1.x);
#pragma unroll
            for (int j = 0; j < 4; j++) acc[4][j] = ffma2(a2, b2[j], acc[4][j]);
            a2 = dup2(a1.y);
#pragma unroll
            for (int j = 0; j < 4; j++) acc[5][j] = ffma2(a2, b2[j], acc[5][j]);
            a2 = dup2(a1.z);
#pragma unroll
            for (int j = 0; j < 4; j++) acc[6][j] = ffma2(a2, b2[j], acc[6][j]);
            a2 = dup2(a1.w);
#pragma unroll
            for (int j = 0; j < 4; j++) acc[7][j] = ffma2(a2, b2[j], acc[7][j]);
        }
        __syncthreads();
    }

    const float bnf = rsqrtf(1.0f + LN_EPS);
    const int c0 = col0 + tx * 8;
    float bias8[8], sc8[8], sh8[8];
#pragma unroll
    for (int j = 0; j < 8; j++) bias8[j] = bias[c0 + j];
    if (HAS_BN) {
#pragma unroll
        for (int j = 0; j < 8; j++) { sc8[j] = scale[c0 + j] * bnf; sh8[j] = shift[c0 + j]; }
    }
#pragma unroll
    for (int i = 0; i < 8; i++) {
        const int r = row0 + ty * 8 + i;
        float out[8];
#pragma unroll
        for (int j = 0; j < 4; j++) unpack2(acc[i][j], out[2*j], out[2*j+1]);
#pragma unroll
        for (int j = 0; j < 8; j++) {
            float v = out[j] + bias8[j];
            if (HAS_BN) v = v * sc8[j] + sh8[j];
            if (RELU)   v = fmaxf(v, 0.f);
            out[j] = v;
        }
        if (HAS_RESID) {
            float4 r0 = *(const float4*)&resid[(size_t)r*ldc + c0];
            float4 r1 = *(const float4*)&resid[(size_t)r*ldc + c0 + 4];
            out[0]+=r0.x; out[1]+=r0.y; out[2]+=r0.z; out[3]+=r0.w;
            out[4]+=r1.x; out[5]+=r1.y; out[6]+=r1.z; out[7]+=r1.w;
        }
        *(float4*)&Cout[(size_t)r*ldc + c0]     = make_float4(out[0],out[1],out[2],out[3]);
        *(float4*)&Cout[(size_t)r*ldc + c0 + 4] = make_float4(out[4],out[5],out[6],out[7]);
    }
}

// ---------------- 64x128 tile variant (bit-identical arithmetic) ----------------
template<bool RELU, bool HAS_RESID, bool HAS_BN>
__global__ __launch_bounds__(128, 4)
void gemm64(const float* __restrict__ A, const float* __restrict__ Bm,
            const float* __restrict__ bias,
            const float* __restrict__ scale, const float* __restrict__ shift,
            const float* __restrict__ resid, float* __restrict__ Cout,
            int lda, int ldb, int ldc, int Kd)
{
    __shared__ float As[16][64];
    __shared__ float Bs[16][128];
    const int tid = threadIdx.x;
    const int tx = tid & 15, ty = tid >> 4;
    const int row0 = blockIdx.x * 64, col0 = blockIdx.y * 128;

    const int f0 = tid * 2, f1 = tid * 2 + 1;
    const int ar0 = f0 >> 2, ak0 = (f0 & 3) * 4;
    const int ar1 = f1 >> 2, ak1 = (f1 & 3) * 4;
    const int g0 = tid * 4;
    const int bk0 = g0 >> 5,       bc0 = (g0 & 31) * 4;
    const int bk1 = (g0+1) >> 5,   bc1 = ((g0+1) & 31) * 4;
    const int bk2 = (g0+2) >> 5,   bc2 = ((g0+2) & 31) * 4;
    const int bk3 = (g0+3) >> 5,   bc3 = ((g0+3) & 31) * 4;

    const float* Ar0 = A + (size_t)(row0 + ar0) * lda;
    const float* Ar1 = A + (size_t)(row0 + ar1) * lda;
    const float* Bp  = Bm + col0;

    unsigned long long acc[8][4];
#pragma unroll
    for (int i = 0; i < 8; i++)
#pragma unroll
        for (int j = 0; j < 4; j++) acc[i][j] = 0ull;

    float4 pa0 = *(const float4*)(Ar0 + ak0);
    float4 pa1 = *(const float4*)(Ar1 + ak1);
    float4 pb0 = *(const float4*)(Bp + (size_t)bk0 * ldb + bc0);
    float4 pb1 = *(const float4*)(Bp + (size_t)bk1 * ldb + bc1);
    float4 pb2 = *(const float4*)(Bp + (size_t)bk2 * ldb + bc2);
    float4 pb3 = *(const float4*)(Bp + (size_t)bk3 * ldb + bc3);

    for (int k0 = 0; k0 < Kd; k0 += 16) {
        As[ak0+0][ar0] = pa0.x; As[ak0+1][ar0] = pa0.y;
        As[ak0+2][ar0] = pa0.z; As[ak0+3][ar0] = pa0.w;
        As[ak1+0][ar1] = pa1.x; As[ak1+1][ar1] = pa1.y;
        As[ak1+2][ar1] = pa1.z; As[ak1+3][ar1] = pa1.w;
        *(float4*)&Bs[bk0][bc0] = pb0;
        *(float4*)&Bs[bk1][bc1] = pb1;
        *(float4*)&Bs[bk2][bc2] = pb2;
        *(float4*)&Bs[bk3][bc3] = pb3;
        __syncthreads();
        if (k0 + 16 < Kd) {
            pa0 = *(const float4*)(Ar0 + k0 + 16 + ak0);
            pa1 = *(const float4*)(Ar1 + k0 + 16 + ak1);
            pb0 = *(const float4*)(Bp + (size_t)(k0 + 16 + bk0) * ldb + bc0);
            pb1 = *(const float4*)(Bp + (size_t)(k0 + 16 + bk1) * ldb + bc1);
            pb2 = *(const float4*)(Bp + (size_t)(k0 + 16 + bk2) * ldb + bc2);
            pb3 = *(const float4*)(Bp + (size_t)(k0 + 16 + bk3) * ldb + bc3);
        }
#pragma unroll
        for (int kk = 0; kk < 16; kk++) {
            float4 a0 = *(const float4*)&As[kk][ty*8];
            float4 a1 = *(const float4*)&As[kk][ty*8+4];
            unsigned long long b2[4];
#pragma unroll
            for (int j = 0; j < 4; j++)
                b2[j] = *(const unsigned long long*)&Bs[kk][tx*8 + 2*j];
            unsigned long long a2;
            a2 = dup2(a0.x);
#pragma unroll
            for (int j = 0; j < 4; j++) acc[0][j] = ffma2(a2, b2[j], acc[0][j]);
            a2 = dup2(a0.y);
#pragma unroll
            for (int j = 0; j < 4; j++) acc[1][j] = ffma2(a2, b2[j], acc[1][j]);
            a2 = dup2(a0.z);
#pragma unroll
            for (int j = 0; j < 4; j++) acc[2][j] = ffma2(a2, b2[j], acc[2][j]);
            a2 = dup2(a0.w);
#pragma unroll
            for (int j = 0; j < 4; j++) acc[3][j] = ffma2(a2, b2[j], acc[3][j]);
            a2 = dup2(a1.x);
#pragma unroll
            for (int j = 0; j < 4; j++) acc[4][j] = ffma2(a2, b2[j], acc[4][j]);
            a2 = dup2(a1.y);
#pragma unroll
            for (int j = 0; j < 4; j++) acc[5][j] = ffma2(a2, b2[j], acc[5][j]);
            a2 = dup2(a1.z);
#pragma unroll
            for (int j = 0; j < 4; j++) acc[6][j] = ffma2(a2, b2[j], acc[6][j]);
            a2 = dup2(a1.w);
#pragma unroll
            for (int j = 0; j < 4; j++) acc[7][j] = ffma2(a2, b2[j], acc[7][j]);
        }
        __syncthreads();
    }

    const float bnf = rsqrtf(1.0f + LN_EPS);
    const int c0 = col0 + tx * 8;
    float bias8[8], sc8[8], sh8[8];
#pragma unroll
    for (int j = 0; j < 8; j++) bias8[j] = bias[c0 + j];
    if (HAS_BN) {
#pragma unroll
        for (int j = 0; j < 8; j++) { sc8[j] = scale[c0 + j] * bnf; sh8[j] = shift[c0 + j]; }
    }
#pragma unroll
    for (int i = 0; i < 8; i++) {
        const int r = row0 + ty * 8 + i;
        float out[8];
#pragma unroll
        for (int j = 0; j < 4; j++) unpack2(acc[i][j], out[2*j], out[2*j+1]);
#pragma unroll
        for (int j = 0; j < 8; j++) {
            float v = out[j] + bias8[j];
            if (HAS_BN) v = v * sc8[j] + sh8[j];
            if (RELU)   v = fmaxf(v, 0.f);
            out[j] = v;
        }
        if (HAS_RESID) {
            float4 r0 = *(const float4*)&resid[(size_t)r*ldc + c0];
            float4 r1 = *(const float4*)&resid[(size_t)r*ldc + c0 + 4];
            out[0]+=r0.x; out[1]+=r0.y; out[2]+=r0.z; out[3]+=r0.w;
            out[4]+=r1.x; out[5]+=r1.y; out[6]+=r1.z; out[7]+=r1.w;
        }
        *(float4*)&Cout[(size_t)r*ldc + c0]     = make_float4(out[0],out[1],out[2],out[3]);
        *(float4*)&Cout[(size_t)r*ldc + c0 + 4] = make_float4(out[4],out[5],out[6],out[7]);
    }
}

// ---------------- weight concat prep ----------------
__global__ void prep_kernel(const float* __restrict__ Ws, const float* __restrict__ Wn,
                            const float* __restrict__ bs)
{
    int idx = blockIdx.x * 256 + threadIdx.x;
    if (idx < NLAYERS * 256 * 512) {
        int i = idx / (256 * 512);
        int rem = idx % (256 * 512);
        int d = rem / 512, col = rem % 512;
        int h = col >> 7, e = col & 127;
        const float* src = (d < 128) ? Ws : Wn;
        d_WCAT[idx] = src[((((size_t)i * NHEADS) + h) * HD + (d & 127)) * HD + e];
    }
    if (idx < NLAYERS * 512) {
        int i = idx / 512, col = idx % 512;
        d_BSCAT[idx] = bs[(i * NHEADS + (col >> 7)) * HD + (col & 127)];
    }
}

// ---------------- KNN: 64 nodes x 4 j-partitions, j-loop unrolled x2 (bit-identical ADJ) ----------------
__global__ __launch_bounds__(256)
void knn_kernel(const float* __restrict__ C, int Ni, int W,
                unsigned long long* __restrict__ ADJ)
{
    __shared__ float2 sc[NMAX];
    __shared__ float sd[64 * 4 * KNN];
    __shared__ int   sj[64 * 4 * KNN];
    const int b = blockIdx.y;
    const int node0 = blockIdx.x * 64;
    const int t = threadIdx.x;
    const int nl = t & 63, part = t >> 6;
    const float2* cb = (const float2*)(C + (size_t)b * Ni * 2);
    for (int idx = t; idx < Ni; idx += 256) sc[idx] = cb[idx];
    __syncthreads();

    const int i = node0 + nl;
    const float2 me = sc[i];
    float bd[KNN]; int bj[KNN];
#pragma unroll
    for (int q = 0; q < KNN; q++) { bd[q] = 3.4e38f; bj[q] = 0x7fffffff; }

    auto try_insert = [&](float d2, int j) {
        if (d2 < bd[KNN-1]) {
#pragma unroll
            for (int q = KNN-1; q > 0; --q) {
                bool prev = d2 < bd[q-1];
                bool here = d2 < bd[q];
                float nb = prev ? bd[q-1] : (here ? d2 : bd[q]);
                int   nj = prev ? bj[q-1] : (here ? j  : bj[q]);
                bd[q] = nb; bj[q] = nj;
            }
            if (d2 < bd[0]) { bd[0] = d2; bj[0] = j; }
        }
    };

    const int jlen = Ni >> 2;          // divisible by 2 for all layers
    const int j0 = part * jlen;
    for (int jj = 0; jj < jlen; jj += 2) {
        int j = j0 + jj;
        float4 p = *(const float4*)(&sc[j]);   // nodes j (x,y) and j+1 (z,w)
        float dx0 = me.x - p.x, dy0 = me.y - p.y;
        float d20 = dx0 * dx0 + dy0 * dy0;
        float dx1 = me.x - p.z, dy1 = me.y - p.w;
        float d21 = dx1 * dx1 + dy1 * dy1;
        try_insert(d20, j);
        try_insert(d21, j + 1);
    }
#pragma unroll
    for (int q = 0; q < KNN; q++) {
        sd[(nl * 4 + part) * KNN + q] = bd[q];
        sj[(nl * 4 + part) * KNN + q] = bj[q];
    }
    __syncthreads();

    if (t < 64) {
        float md[KNN]; int mj[KNN];
#pragma unroll
        for (int q = 0; q < KNN; q++) { md[q] = 3.4e38f; mj[q] = 0x7fffffff; }
        for (int p = 0; p < 4; p++) {
#pragma unroll
            for (int q = 0; q < KNN; q++) {
                float d2 = sd[(t * 4 + p) * KNN + q];
                int   j  = sj[(t * 4 + p) * KNN + q];
                if (d2 < md[KNN-1]) {
#pragma unroll
                    for (int w = KNN-1; w > 0; --w) {
                        bool prev = d2 < md[w-1];
                        bool here = d2 < md[w];
                        float nb = prev ? md[w-1] : (here ? d2 : md[w]);
                        int   nj = prev ? mj[w-1] : (here ? j  : mj[w]);
                        md[w] = nb; mj[w] = nj;
                    }
                    if (d2 < md[0]) { md[0] = d2; mj[0] = j; }
                }
            }
        }
        const int gi = node0 + t;
        const size_t rowbase = ((size_t)b * Ni + gi) * W;
#pragma unroll
        for (int q = 0; q < KNN; q++) {
            int j = mj[q];
            atomicOr(&ADJ[rowbase + (j >> 6)], 1ull << (j & 63));
            atomicOr(&ADJ[((size_t)b * Ni + j) * W + (gi >> 6)], 1ull << (gi & 63));
        }
    }
}

__global__ void deg_kernel(const unsigned long long* __restrict__ ADJ, int W, int total,
                           float* __restrict__ DINV, float* __restrict__ RDEG)
{
    int g = blockIdx.x*256 + threadIdx.x;
    if (g >= total) return;
    int d = 0;
    const unsigned long long* row = ADJ + (size_t)g*W;
    for (int w = 0; w < W; w++) d += __popcll(row[w]);
    float fd = (float)d;
    DINV[g] = rsqrtf(fd);
    RDEG[g] = 1.0f / fd;
}

// ---------------- LayerNorm (exact R8 structure) ----------------
__global__ __launch_bounds__(128)
void ln_kernel(const float* __restrict__ X, const float* __restrict__ gg,
               const float* __restrict__ bb, float* __restrict__ out, int ldo)
{
    const size_t node = blockIdx.x;
    const int t = threadIdx.x;
    float v = X[node*HD + t];
    __shared__ float sh[4];
    float s = v;
#pragma unroll
    for (int o = 16; o > 0; o >>= 1) s += __shfl_xor_sync(0xffffffffu, s, o);
    if ((t & 31) == 0) sh[t >> 5] = s;
    __syncthreads();
    float mean = (sh[0]+sh[1]+sh[2]+sh[3]) * (1.f/HD);
    __syncthreads();
    float dd = v - mean;
    float q = dd*dd;
#pragma unroll
    for (int o = 16; o > 0; o >>= 1) q += __shfl_xor_sync(0xffffffffu, q, o);
    if ((t & 31) == 0) sh[t >> 5] = q;
    __syncthreads();
    float var = (sh[0]+sh[1]+sh[2]+sh[3]) * (1.f/HD);
    out[node*(size_t)ldo + t] = dd * rsqrtf(var + LN_EPS) * gg[t] + bb[t];
}

// ---------------- neighbor mean aggregation over bitset ----------------
__global__ __launch_bounds__(128)
void agg_kernel(float* __restrict__ XM, const unsigned long long* __restrict__ ADJ,
                const float* __restrict__ RDEG, int Ni, int W)
{
    const int g = blockIdx.x;
    const int t = threadIdx.x;
    const int b = g / Ni;
    const size_t base = (size_t)b*Ni;
    const unsigned long long* row = ADJ + (size_t)g*W;
    float acc = 0.f;
    for (int w = 0; w < W; w++) {
        unsigned long long word = row[w];
        while (word) {
            int bit = __ffsll((long long)word) - 1;
            word &= word - 1;
            int j = w*64 + bit;
            acc += XM[(base + j)*2*HD + t];
        }
    }
    XM[(size_t)g*2*HD + HD + t] = acc * RDEG[g];
}

// ---------------- Y = x @ Wq (exact R8 structure) ----------------
__global__ void yq_kernel(const float* __restrict__ X, const float* __restrict__ Wq,
                          float* __restrict__ Y, int total)
{
    int g = blockIdx.x*8 + threadIdx.y;
    if (g >= total) return;
    int lane = threadIdx.x;
    float4 xv = *(const float4*)&X[(size_t)g*HD + lane*4];
    float4 wv = *(const float4*)&Wq[lane*4];
    float a = xv.x*wv.x + xv.y*wv.y + xv.z*wv.z + xv.w*wv.w;
#pragma unroll
    for (int o = 16; o > 0; o >>= 1) a += __shfl_xor_sync(0xffffffffu, a, o);
    if (lane == 0) Y[g] = a;
}

// ---------------- fused score + bitonic top-k (score arithmetic identical to score_kernel) ----------------
__global__ __launch_bounds__(1024)
void topk_kernel(const unsigned long long* __restrict__ ADJ, int W,
                 const float* __restrict__ DINV, const float* __restrict__ Y,
                 const float* __restrict__ bqp,
                 int Ni, int kk,
                 int* __restrict__ TOPI, float* __restrict__ TOPV)
{
    __shared__ float sv[NMAX];
    __shared__ int   si[NMAX];
    const int b = blockIdx.x;
    const int tid = threadIdx.x;
    const size_t base = (size_t)b * Ni;
    const float bqv = bqp[0];
    for (int i = tid; i < Ni; i += 1024) {
        // identical per-node expression to the old score_kernel
        const unsigned long long* row = ADJ + (base + i) * W;
        float acc = 0.f;
        for (int w = 0; w < W; w++) {
            unsigned long long word = row[w];
            while (word) {
                int bit = __ffsll((long long)word) - 1;
                word &= word - 1;
                int j = w*64 + bit;
                acc += DINV[base + j] * Y[base + j];
            }
        }
        sv[i] = DINV[base + i] * acc + bqv;
        si[i] = i;
    }
    __syncthreads();
    for (int k = 2; k <= Ni; k <<= 1) {
        for (int j = k >> 1; j > 0; j >>= 1) {
            for (int i = tid; i < Ni; i += 1024) {
                int l = i ^ j;
                if (l > i) {
                    bool up = ((i & k) == 0);
                    float vi = sv[i], vl = sv[l];
                    int ii = si[i], il = si[l];
                    bool iAfterL = (vi < vl) || (vi == vl && ii > il);
                    bool dosw = up ? iAfterL : !iAfterL;
                    if (dosw) { sv[i] = vl; sv[l] = vi; si[i] = il; si[l] = ii; }
                }
            }
            __syncthreads();
        }
    }
    for (int r = tid; r < kk; r += 1024) {
        TOPI[(size_t)b*kk + r] = si[r];
        TOPV[(size_t)b*kk + r] = sv[r];
    }
}

// ---------------- gather + tanh gate + (optional) next-layer ln1 into XM (bit-identical LN) ----------------
__global__ __launch_bounds__(128)
void gather_kernel(const float* __restrict__ Xo, const float* __restrict__ Co,
                   float* __restrict__ Xn, float* __restrict__ Cn,
                   const int* __restrict__ TOPI, const float* __restrict__ TOPV,
                   int Ni, int kk,
                   const float* __restrict__ lng, const float* __restrict__ lnb,
                   float* __restrict__ lnout)
{
    __shared__ float sh[4];
    const int b = blockIdx.y, r = blockIdx.x, t = threadIdx.x;
    const int src = TOPI[(size_t)b*kk + r];
    const float gte = tanhf(TOPV[(size_t)b*kk + r]);
    const size_t node = (size_t)b*kk + r;
    float v = Xo[((size_t)b*Ni + src)*HD + t] * gte;
    Xn[node*HD + t] = v;
    if (t < 2) Cn[node*2 + t] = Co[((size_t)b*Ni + src)*2 + t];

    if (lng) {
        // exact ln_kernel reduction structure — bit-identical to a separate ln pass
        float s = v;
#pragma unroll
        for (int o = 16; o > 0; o >>= 1) s += __shfl_xor_sync(0xffffffffu, s, o);
        if ((t & 31) == 0) sh[t >> 5] = s;
        __syncthreads();
        float mean = (sh[0]+sh[1]+sh[2]+sh[3]) * (1.f/HD);
        __syncthreads();
        float dd = v - mean;
        float q = dd*dd;
#pragma unroll
        for (int o = 16; o > 0; o >>= 1) q += __shfl_xor_sync(0xffffffffu, q, o);
        if ((t & 31) == 0) sh[t >> 5] = q;
        __syncthreads();
        float var = (sh[0]+sh[1]+sh[2]+sh[3]) * (1.f/HD);
        lnout[node*(size_t)(2*HD) + t] = dd * rsqrtf(var + LN_EPS) * lng[t] + lnb[t];
    }
}

// ---------------- readout ----------------
__global__ __launch_bounds__(128)
void readout_kernel(const float* __restrict__ Xp, int kk, float* __restrict__ PICKS)
{
    const int b = blockIdx.x, t = threadIdx.x;
    float mx = -3.4e38f, sm = 0.f;
    for (int r = 0; r < kk; r++) {
        float v = Xp[((size_t)b*kk + r)*HD + t];
        mx = fmaxf(mx, v);
        sm += v;
    }
    PICKS[b*2*HD + t]      += mx;
    PICKS[b*2*HD + HD + t] += sm / (float)kk;
}

// ---------------- final MLP ----------------
__global__ __launch_bounds__(256)
void final_kernel(const float* __restrict__ Wf1, const float* __restrict__ bf1,
                  const float* __restrict__ Wf2, const float* __restrict__ bf2,
                  float* __restrict__ out)
{
    __shared__ float f1s[BB*HD];
    const int tid = threadIdx.x;
    for (int o = tid; o < BB*HD; o += 256) {
        int b = o >> 7, c = o & 127;
        float a = bf1[c];
        const float* pr = &d_PICKS[b*2*HD];
        for (int k = 0; k < 2*HD; k++) a += pr[k] * Wf1[k*HD + c];
        f1s[o] = fmaxf(a, 0.f);
    }
    __syncthreads();
    int b = tid >> 5, c = tid & 31;
    float a = bf2[c];
    for (int k = 0; k < HD; k++) a += f1s[b*HD + k] * Wf2[k*32 + c];
    out[b*32 + c] = fmaxf(a, 0.f);
}

// ---------------- host orchestration ----------------
#define GEMM_CALL(R, RS, BN, M, NB, Aa, Bb, bi, sc, sh, re, Co, la, lb, lc, Kd)          \
    do {                                                                                  \
        if ((M) >= 12288)                                                                 \
            gemm128<R,RS,BN><<<dim3((M)/128, (NB)), 256>>>(Aa, Bb, bi, sc, sh, re, Co,    \
                                                           la, lb, lc, Kd);               \
        else                                                                              \
            gemm64<R,RS,BN><<<dim3((M)/64, (NB)), 128>>>(Aa, Bb, bi, sc, sh, re, Co,      \
                                                         la, lb, lc, Kd);                 \
    } while (0)

extern "C" void kernel_launch(void* const* d_in, const int* in_sizes, int n_in,
                              void* d_out, int out_size)
{
    const float* feats = (const float*)d_in[0];
    const float* cent  = (const float*)d_in[1];
    const float* Wp1   = (const float*)d_in[2];
    const float* bp1   = (const float*)d_in[3];
    const float* bn_g  = (const float*)d_in[4];
    const float* bn_b  = (const float*)d_in[5];
    const float* Wp2   = (const float*)d_in[6];
    const float* bp2   = (const float*)d_in[7];
    const float* g1    = (const float*)d_in[8];
    const float* be1   = (const float*)d_in[9];
    const float* g2    = (const float*)d_in[10];
    const float* be2   = (const float*)d_in[11];
    const float* Ws    = (const float*)d_in[12];
    const float* Wn    = (const float*)d_in[13];
    const float* bs    = (const float*)d_in[14];
    const float* Wg    = (const float*)d_in[15];
    const float* bg    = (const float*)d_in[16];
    const float* W1    = (const float*)d_in[17];
    const float* b1    = (const float*)d_in[18];
    const float* W2    = (const float*)d_in[19];
    const float* b2    = (const float*)d_in[20];
    const float* Wq    = (const float*)d_in[21];
    const float* bq    = (const float*)d_in[22];
    const float* Wf1   = (const float*)d_in[23];
    const float* bf1   = (const float*)d_in[24];
    const float* Wf2   = (const float*)d_in[25];
    const float* bf2   = (const float*)d_in[26];

    float *Xa, *Xb, *XM, *XN, *T1, *Hb, *Ca, *Cb, *DINV, *RDEG, *Y, *TOPV, *PICKS;
    float *WCAT, *BSCAT;
    int* TOPI;
    unsigned long long* ADJ;
    cudaGetSymbolAddress((void**)&Xa, d_X);
    cudaGetSymbolAddress((void**)&Xb, d_XG);
    cudaGetSymbolAddress((void**)&XM, d_XM);
    cudaGetSymbolAddress((void**)&XN, d_XN);
    cudaGetSymbolAddress((void**)&T1, d_T1);
    cudaGetSymbolAddress((void**)&Hb, d_H);
    cudaGetSymbolAddress((void**)&Ca, d_C);
    cudaGetSymbolAddress((void**)&Cb, d_CG);
    cudaGetSymbolAddress((void**)&WCAT, d_WCAT);
    cudaGetSymbolAddress((void**)&BSCAT, d_BSCAT);
    cudaGetSymbolAddress((void**)&ADJ, d_ADJ);
    cudaGetSymbolAddress((void**)&DINV, d_DINV);
    cudaGetSymbolAddress((void**)&RDEG, d_RDEG);
    cudaGetSymbolAddress((void**)&Y,  d_Y);
    cudaGetSymbolAddress((void**)&TOPI, d_TOPI);
    cudaGetSymbolAddress((void**)&TOPV, d_TOPV);
    cudaGetSymbolAddress((void**)&PICKS, d_PICKS);

    const int M0 = MAXNODES;   // 16384 rows

    // weight concat prep
    prep_kernel<<<(NLAYERS*256*512 + 255)/256, 256>>>(Ws, Wn, bs);

    // preconv: T1 = relu(bn(feats@Wp1+bp1)); X = T1@Wp2 + bp2
    GEMM_CALL(true, false, true, M0, 1,
              feats, Wp1, bp1, bn_g, bn_b, nullptr, T1, 512, 128, 128, 512);
    GEMM_CALL(false, false, false, M0, 1,
              T1, Wp2, bp2, nullptr, nullptr, nullptr, Xa, 128, 128, 128, 128);

    cudaMemcpyAsync(Ca, cent, (size_t)M0*2*sizeof(float), cudaMemcpyDeviceToDevice);
    cudaMemsetAsync(PICKS, 0, BB*2*HD*sizeof(float));

    // layer-0 ln1 -> XM[:, :128] (exact R8 kernel)
    ln_kernel<<<M0, 128>>>(Xa, g1, be1, XM, 2*HD);

    float *Xcur = Xa, *Xnext = Xb, *Ccur = Ca, *Cnext = Cb;
    int Ni = NMAX;
    for (int i = 0; i < NLAYERS; i++) {
        const int W = Ni / 64;
        const int total = BB * Ni;
        const int kk = Ni / 2;

        cudaMemsetAsync(ADJ, 0, (size_t)total * W * sizeof(unsigned long long));
        knn_kernel<<<dim3(Ni/64, BB), 256>>>(Ccur, Ni, W, ADJ);
        deg_kernel<<<(total+255)/256, 256>>>(ADJ, W, total, DINV, RDEG);

        // neighbor mean into XM[:, 128:256] (XM[:, :128] holds ln1 already)
        agg_kernel<<<total, 128>>>(XM, ADJ, RDEG, Ni, W);

        // fused 4-head GEMM: Hb = relu([XN|Mg] @ WCAT + BSCAT)   [total x 512]
        GEMM_CALL(true, false, false, total, 4,
                  XM, WCAT + (size_t)i*256*512, BSCAT + (size_t)i*512,
                  nullptr, nullptr, nullptr, Hb, 256, 512, 512, 256);
        // out-proj + residual: X += Hb @ Wg + bg
        GEMM_CALL(false, true, false, total, 1,
                  Hb, Wg + (size_t)i*NHEADS*HD*HD, bg + i*HD,
                  nullptr, nullptr, Xcur, Xcur, 512, 128, 128, 512);

        // FFN
        ln_kernel<<<total, 128>>>(Xcur, g2 + i*HD, be2 + i*HD, XN, HD);
        GEMM_CALL(true, false, false, total, 1,
                  XN, W1 + (size_t)i*HD*HD, b1 + i*HD,
                  nullptr, nullptr, nullptr, T1, 128, 128, 128, 128);
        GEMM_CALL(false, true, false, total, 1,
                  T1, W2 + (size_t)i*HD*HD, b2 + i*HD,
                  nullptr, nullptr, Xcur, Xcur, 128, 128, 128, 128);

        // SAGPool: yq, fused score+topk, gather(+next ln1), readout
        yq_kernel<<<(total+7)/8, dim3(32, 8)>>>(Xcur, Wq + (size_t)i*HD, Y, total);
        topk_kernel<<<BB, 1024>>>(ADJ, W, DINV, Y, bq + i, Ni, kk, TOPI, TOPV);
        if (i + 1 < NLAYERS)
            gather_kernel<<<dim3(kk, BB), 128>>>(Xcur, Ccur, Xnext, Cnext, TOPI, TOPV,
                                                 Ni, kk, g1 + (i+1)*HD, be1 + (i+1)*HD, XM);
        else
            gather_kernel<<<dim3(kk, BB), 128>>>(Xcur, Ccur, Xnext, Cnext, TOPI, TOPV,
                                                 Ni, kk, nullptr, nullptr, nullptr);
        readout_kernel<<<BB, 128>>>(Xnext, kk, PICKS);

        // ping-pong
        float* t;
        t = Xcur; Xcur = Xnext; Xnext = t;
        t = Ccur; Ccur = Cnext; Cnext = t;
        Ni = kk;
    }

    final_kernel<<<1, 256>>>(Wf1, bf1, Wf2, bf2, (float*)d_out);
}

// round 13
// speedup vs baseline: 1.0587x; 1.0587x over previous
#include <cuda_runtime.h>
#include <math.h>

#define BB 8
#define NMAX 2048
#define HD 128
#define NHEADS 4
#define NLAYERS 3
#define KNN 8
#define MAXNODES (BB*NMAX)
#define LN_EPS 1e-5f

// ---------------- device scratch ----------------
__device__ __align__(256) float d_X [MAXNODES*HD];      // ping
__device__ __align__(256) float d_XG[MAXNODES*HD];      // pong
__device__ __align__(256) float d_XM[MAXNODES*2*HD];    // [XN | Mg] concat, stride 256
__device__ __align__(256) float d_XN[MAXNODES*HD];      // ln2 output
__device__ __align__(256) float d_T1[MAXNODES*HD];
__device__ __align__(256) float d_H [MAXNODES*NHEADS*HD];
__device__ __align__(256) float d_C [MAXNODES*2];
__device__ __align__(256) float d_CG[MAXNODES*2];
__device__ __align__(256) float d_WCAT[NLAYERS*256*512];
__device__ __align__(256) float d_BSCAT[NLAYERS*512];
__device__ unsigned long long d_ADJ[(size_t)MAXNODES*(NMAX/64)];
__device__ float d_DINV[MAXNODES];
__device__ float d_Y  [MAXNODES];
__device__ float d_S  [MAXNODES];
__device__ int   d_TOPI[BB*(NMAX/2)];
__device__ float d_TOPV[BB*(NMAX/2)];
__device__ float d_PICKS[BB*2*HD];
__device__ float d_RPART[BB*8*2*HD];

// ---------------- f32x2 helpers ----------------
__device__ __forceinline__ unsigned long long ffma2(unsigned long long a,
                                                    unsigned long long b,
                                                    unsigned long long c) {
    unsigned long long d;
    asm("fma.rn.f32x2 %0, %1, %2, %3;" : "=l"(d) : "l"(a), "l"(b), "l"(c));
    return d;
}
__device__ __forceinline__ unsigned long long dup2(float a) {
    unsigned long long d; unsigned int u = __float_as_uint(a);
    asm("mov.b64 %0, {%1, %1};" : "=l"(d) : "r"(u));
    return d;
}
__device__ __forceinline__ void unpack2(unsigned long long v, float& lo, float& hi) {
    unsigned int l, h;
    asm("mov.b64 {%0, %1}, %2;" : "=r"(l), "=r"(h) : "l"(v));
    lo = __uint_as_float(l); hi = __uint_as_float(h);
}

// ---------------- 128x128 tiled fp32 GEMM (R2-proven) ----------------
template<bool RELU, bool HAS_RESID, bool HAS_BN>
__global__ __launch_bounds__(256, 2)
void gemm128(const float* __restrict__ A, const float* __restrict__ Bm,
             const float* __restrict__ bias,
             const float* __restrict__ scale, const float* __restrict__ shift,
             const float* __restrict__ resid, float* __restrict__ Cout,
             int lda, int ldb, int ldc, int Kd)
{
    __shared__ float As[16][128];
    __shared__ float Bs[16][128];
    const int tid = threadIdx.x;
    const int tx = tid & 15, ty = tid >> 4;
    const int row0 = blockIdx.x * 128, col0 = blockIdx.y * 128;

    const int f0 = tid * 2, f1 = tid * 2 + 1;
    const int ar0 = f0 >> 2, ak0 = (f0 & 3) * 4;
    const int ar1 = f1 >> 2, ak1 = (f1 & 3) * 4;
    const int bk0 = f0 >> 5, bc0 = (f0 & 31) * 4;
    const int bk1 = f1 >> 5, bc1 = (f1 & 31) * 4;

    const float* Ar0 = A + (size_t)(row0 + ar0) * lda;
    const float* Ar1 = A + (size_t)(row0 + ar1) * lda;
    const float* Bp  = Bm + col0;

    unsigned long long acc[8][4];
#pragma unroll
    for (int i = 0; i < 8; i++)
#pragma unroll
        for (int j = 0; j < 4; j++) acc[i][j] = 0ull;

    float4 pa0 = *(const float4*)(Ar0 + ak0);
    float4 pa1 = *(const float4*)(Ar1 + ak1);
    float4 pb0 = *(const float4*)(Bp + (size_t)bk0 * ldb + bc0);
    float4 pb1 = *(const float4*)(Bp + (size_t)bk1 * ldb + bc1);

    for (int k0 = 0; k0 < Kd; k0 += 16) {
        As[ak0+0][ar0] = pa0.x; As[ak0+1][ar0] = pa0.y;
        As[ak0+2][ar0] = pa0.z; As[ak0+3][ar0] = pa0.w;
        As[ak1+0][ar1] = pa1.x; As[ak1+1][ar1] = pa1.y;
        As[ak1+2][ar1] = pa1.z; As[ak1+3][ar1] = pa1.w;
        *(float4*)&Bs[bk0][bc0] = pb0;
        *(float4*)&Bs[bk1][bc1] = pb1;
        __syncthreads();
        if (k0 + 16 < Kd) {
            pa0 = *(const float4*)(Ar0 + k0 + 16 + ak0);
            pa1 = *(const float4*)(Ar1 + k0 + 16 + ak1);
            pb0 = *(const float4*)(Bp + (size_t)(k0 + 16 + bk0) * ldb + bc0);
            pb1 = *(const float4*)(Bp + (size_t)(k0 + 16 + bk1) * ldb + bc1);
        }
#pragma unroll
        for (int kk = 0; kk < 16; kk++) {
            float4 a0 = *(const float4*)&As[kk][ty*8];
            float4 a1 = *(const float4*)&As[kk][ty*8+4];
            unsigned long long b2[4];
#pragma unroll
            for (int j = 0; j < 4; j++)
                b2[j] = *(const unsigned long long*)&Bs[kk][tx*8 + 2*j];
            unsigned long long a2;
            a2 = dup2(a0.x);
#pragma unroll
            for (int j = 0; j < 4; j++) acc[0][j] = ffma2(a2, b2[j], acc[0][j]);
            a2 = dup2(a0.y);
#pragma unroll
            for (int j = 0; j < 4; j++) acc[1][j] = ffma2(a2, b2[j], acc[1][j]);
            a2 = dup2(a0.z);
#pragma unroll
            for (int j = 0; j < 4; j++) acc[2][j] = ffma2(a2, b2[j], acc[2][j]);
            a2 = dup2(a0.w);
#pragma unroll
            for (int j = 0; j < 4; j++) acc[3][j] = ffma2(a2, b2[j], acc[3][j]);
            a2 = dup2(a1.x);
#pragma unroll
            for (int j = 0; j < 4; j++) acc[4][j] = ffma2(a2, b2[j], acc[4][j]);
            a2 = dup2(a1.y);
#pragma unroll
            for (int j = 0; j < 4; j++) acc[5][j] = ffma2(a2, b2[j], acc[5][j]);
            a2 = dup2(a1.z);
#pragma unroll
            for (int j = 0; j < 4; j++) acc[6][j] = ffma2(a2, b2[j], acc[6][j]);
            a2 = dup2(a1.w);
#pragma unroll
            for (int j = 0; j < 4; j++) acc[7][j] = ffma2(a2, b2[j], acc[7][j]);
        }
        __syncthreads();
    }

    const float bnf = rsqrtf(1.0f + LN_EPS);
    const int c0 = col0 + tx * 8;
    float bias8[8], sc8[8], sh8[8];
#pragma unroll
    for (int j = 0; j < 8; j++) bias8[j] = bias[c0 + j];
    if (HAS_BN) {
#pragma unroll
        for (int j = 0; j < 8; j++) { sc8[j] = scale[c0 + j] * bnf; sh8[j] = shift[c0 + j]; }
    }
#pragma unroll
    for (int i = 0; i < 8; i++) {
        const int r = row0 + ty * 8 + i;
        float out[8];
#pragma unroll
        for (int j = 0; j < 4; j++) unpack2(acc[i][j], out[2*j], out[2*j+1]);
#pragma unroll
        for (int j = 0; j < 8; j++) {
            float v = out[j] + bias8[j];
            if (HAS_BN) v = v * sc8[j] + sh8[j];
            if (RELU)   v = fmaxf(v, 0.f);
            out[j] = v;
        }
        if (HAS_RESID) {
            float4 r0 = *(const float4*)&resid[(size_t)r*ldc + c0];
            float4 r1 = *(const float4*)&resid[(size_t)r*ldc + c0 + 4];
            out[0]+=r0.x; out[1]+=r0.y; out[2]+=r0.z; out[3]+=r0.w;
            out[4]+=r1.x; out[5]+=r1.y; out[6]+=r1.z; out[7]+=r1.w;
        }
        *(float4*)&Cout[(size_t)r*ldc + c0]     = make_float4(out[0],out[1],out[2],out[3]);
        *(float4*)&Cout[(size_t)r*ldc + c0 + 4] = make_float4(out[4],out[5],out[6],out[7]);
    }
}

// ---------------- 64x128 tile variant (bit-identical arithmetic) ----------------
template<bool RELU, bool HAS_RESID, bool HAS_BN>
__global__ __launch_bounds__(128, 4)
void gemm64(const float* __restrict__ A, const float* __restrict__ Bm,
            const float* __restrict__ bias,
            const float* __restrict__ scale, const float* __restrict__ shift,
            const float* __restrict__ resid, float* __restrict__ Cout,
            int lda, int ldb, int ldc, int Kd)
{
    __shared__ float As[16][64];
    __shared__ float Bs[16][128];
    const int tid = threadIdx.x;
    const int tx = tid & 15, ty = tid >> 4;
    const int row0 = blockIdx.x * 64, col0 = blockIdx.y * 128;

    const int f0 = tid * 2, f1 = tid * 2 + 1;
    const int ar0 = f0 >> 2, ak0 = (f0 & 3) * 4;
    const int ar1 = f1 >> 2, ak1 = (f1 & 3) * 4;
    const int g0 = tid * 4;
    const int bk0 = g0 >> 5,       bc0 = (g0 & 31) * 4;
    const int bk1 = (g0+1) >> 5,   bc1 = ((g0+1) & 31) * 4;
    const int bk2 = (g0+2) >> 5,   bc2 = ((g0+2) & 31) * 4;
    const int bk3 = (g0+3) >> 5,   bc3 = ((g0+3) & 31) * 4;

    const float* Ar0 = A + (size_t)(row0 + ar0) * lda;
    const float* Ar1 = A + (size_t)(row0 + ar1) * lda;
    const float* Bp  = Bm + col0;

    unsigned long long acc[8][4];
#pragma unroll
    for (int i = 0; i < 8; i++)
#pragma unroll
        for (int j = 0; j < 4; j++) acc[i][j] = 0ull;

    float4 pa0 = *(const float4*)(Ar0 + ak0);
    float4 pa1 = *(const float4*)(Ar1 + ak1);
    float4 pb0 = *(const float4*)(Bp + (size_t)bk0 * ldb + bc0);
    float4 pb1 = *(const float4*)(Bp + (size_t)bk1 * ldb + bc1);
    float4 pb2 = *(const float4*)(Bp + (size_t)bk2 * ldb + bc2);
    float4 pb3 = *(const float4*)(Bp + (size_t)bk3 * ldb + bc3);

    for (int k0 = 0; k0 < Kd; k0 += 16) {
        As[ak0+0][ar0] = pa0.x; As[ak0+1][ar0] = pa0.y;
        As[ak0+2][ar0] = pa0.z; As[ak0+3][ar0] = pa0.w;
        As[ak1+0][ar1] = pa1.x; As[ak1+1][ar1] = pa1.y;
        As[ak1+2][ar1] = pa1.z; As[ak1+3][ar1] = pa1.w;
        *(float4*)&Bs[bk0][bc0] = pb0;
        *(float4*)&Bs[bk1][bc1] = pb1;
        *(float4*)&Bs[bk2][bc2] = pb2;
        *(float4*)&Bs[bk3][bc3] = pb3;
        __syncthreads();
        if (k0 + 16 < Kd) {
            pa0 = *(const float4*)(Ar0 + k0 + 16 + ak0);
            pa1 = *(const float4*)(Ar1 + k0 + 16 + ak1);
            pb0 = *(const float4*)(Bp + (size_t)(k0 + 16 + bk0) * ldb + bc0);
            pb1 = *(const float4*)(Bp + (size_t)(k0 + 16 + bk1) * ldb + bc1);
            pb2 = *(const float4*)(Bp + (size_t)(k0 + 16 + bk2) * ldb + bc2);
            pb3 = *(const float4*)(Bp + (size_t)(k0 + 16 + bk3) * ldb + bc3);
        }
#pragma unroll
        for (int kk = 0; kk < 16; kk++) {
            float4 a0 = *(const float4*)&As[kk][ty*8];
            float4 a1 = *(const float4*)&As[kk][ty*8+4];
            unsigned long long b2[4];
#pragma unroll
            for (int j = 0; j < 4; j++)
                b2[j] = *(const unsigned long long*)&Bs[kk][tx*8 + 2*j];
            unsigned long long a2;
            a2 = dup2(a0.x);
#pragma unroll
            for (int j = 0; j < 4; j++) acc[0][j] = ffma2(a2, b2[j], acc[0][j]);
            a2 = dup2(a0.y);
#pragma unroll
            for (int j = 0; j < 4; j++) acc[1][j] = ffma2(a2, b2[j], acc[1][j]);
            a2 = dup2(a0.z);
#pragma unroll
            for (int j = 0; j < 4; j++) acc[2][j] = ffma2(a2, b2[j], acc[2][j]);
            a2 = dup2(a0.w);
#pragma unroll
            for (int j = 0; j < 4; j++) acc[3][j] = ffma2(a2, b2[j], acc[3][j]);
            a2 = dup2(a1.x);
#pragma unroll
            for (int j = 0; j < 4; j++) acc[4][j] = ffma2(a2, b2[j], acc[4][j]);
            a2 = dup2(a1.y);
#pragma unroll
            for (int j = 0; j < 4; j++) acc[5][j] = ffma2(a2, b2[j], acc[5][j]);
            a2 = dup2(a1.z);
#pragma unroll
            for (int j = 0; j < 4; j++) acc[6][j] = ffma2(a2, b2[j], acc[6][j]);
            a2 = dup2(a1.w);
#pragma unroll
            for (int j = 0; j < 4; j++) acc[7][j] = ffma2(a2, b2[j], acc[7][j]);
        }
        __syncthreads();
    }

    const float bnf = rsqrtf(1.0f + LN_EPS);
    const int c0 = col0 + tx * 8;
    float bias8[8], sc8[8], sh8[8];
#pragma unroll
    for (int j = 0; j < 8; j++) bias8[j] = bias[c0 + j];
    if (HAS_BN) {
#pragma unroll
        for (int j = 0; j < 8; j++) { sc8[j] = scale[c0 + j] * bnf; sh8[j] = shift[c0 + j]; }
    }
#pragma unroll
    for (int i = 0; i < 8; i++) {
        const int r = row0 + ty * 8 + i;
        float out[8];
#pragma unroll
        for (int j = 0; j < 4; j++) unpack2(acc[i][j], out[2*j], out[2*j+1]);
#pragma unroll
        for (int j = 0; j < 8; j++) {
            float v = out[j] + bias8[j];
            if (HAS_BN) v = v * sc8[j] + sh8[j];
            if (RELU)   v = fmaxf(v, 0.f);
            out[j] = v;
        }
        if (HAS_RESID) {
            float4 r0 = *(const float4*)&resid[(size_t)r*ldc + c0];
            float4 r1 = *(const float4*)&resid[(size_t)r*ldc + c0 + 4];
            out[0]+=r0.x; out[1]+=r0.y; out[2]+=r0.z; out[3]+=r0.w;
            out[4]+=r1.x; out[5]+=r1.y; out[6]+=r1.z; out[7]+=r1.w;
        }
        *(float4*)&Cout[(size_t)r*ldc + c0]     = make_float4(out[0],out[1],out[2],out[3]);
        *(float4*)&Cout[(size_t)r*ldc + c0 + 4] = make_float4(out[4],out[5],out[6],out[7]);
    }
}

// ---------------- weight concat prep ----------------
__global__ void prep_kernel(const float* __restrict__ Ws, const float* __restrict__ Wn,
                            const float* __restrict__ bs)
{
    int idx = blockIdx.x * 256 + threadIdx.x;
    if (idx < NLAYERS * 256 * 512) {
        int i = idx / (256 * 512);
        int rem = idx % (256 * 512);
        int d = rem / 512, col = rem % 512;
        int h = col >> 7, e = col & 127;
        const float* src = (d < 128) ? Ws : Wn;
        d_WCAT[idx] = src[((((size_t)i * NHEADS) + h) * HD + (d & 127)) * HD + e];
    }
    if (idx < NLAYERS * 512) {
        int i = idx / 512, col = idx % 512;
        d_BSCAT[idx] = bs[(i * NHEADS + (col >> 7)) * HD + (col & 127)];
    }
}

// ---------------- KNN (exact R8 kernel, bit-identical ADJ) ----------------
__global__ __launch_bounds__(256)
void knn_kernel(const float* __restrict__ C, int Ni, int W,
                unsigned long long* __restrict__ ADJ)
{
    __shared__ float2 sc[NMAX];
    __shared__ float sd[64 * 4 * KNN];
    __shared__ int   sj[64 * 4 * KNN];
    const int b = blockIdx.y;
    const int node0 = blockIdx.x * 64;
    const int t = threadIdx.x;
    const int nl = t & 63, part = t >> 6;
    const float2* cb = (const float2*)(C + (size_t)b * Ni * 2);
    for (int idx = t; idx < Ni; idx += 256) sc[idx] = cb[idx];
    __syncthreads();

    const int i = node0 + nl;
    const float2 me = sc[i];
    float bd[KNN]; int bj[KNN];
#pragma unroll
    for (int q = 0; q < KNN; q++) { bd[q] = 3.4e38f; bj[q] = 0x7fffffff; }

    const int jlen = Ni >> 2;
    const int j0 = part * jlen;
    for (int jj = 0; jj < jlen; jj++) {
        int j = j0 + jj;
        float dx = me.x - sc[j].x, dy = me.y - sc[j].y;
        float d2 = dx * dx + dy * dy;
        if (d2 < bd[KNN-1]) {
#pragma unroll
            for (int q = KNN-1; q > 0; --q) {
                bool prev = d2 < bd[q-1];
                bool here = d2 < bd[q];
                float nb = prev ? bd[q-1] : (here ? d2 : bd[q]);
                int   nj = prev ? bj[q-1] : (here ? j  : bj[q]);
                bd[q] = nb; bj[q] = nj;
            }
            if (d2 < bd[0]) { bd[0] = d2; bj[0] = j; }
        }
    }
#pragma unroll
    for (int q = 0; q < KNN; q++) {
        sd[(nl * 4 + part) * KNN + q] = bd[q];
        sj[(nl * 4 + part) * KNN + q] = bj[q];
    }
    __syncthreads();

    if (t < 64) {
        float md[KNN]; int mj[KNN];
#pragma unroll
        for (int q = 0; q < KNN; q++) { md[q] = 3.4e38f; mj[q] = 0x7fffffff; }
        for (int p = 0; p < 4; p++) {
#pragma unroll
            for (int q = 0; q < KNN; q++) {
                float d2 = sd[(t * 4 + p) * KNN + q];
                int   j  = sj[(t * 4 + p) * KNN + q];
                if (d2 < md[KNN-1]) {
#pragma unroll
                    for (int w = KNN-1; w > 0; --w) {
                        bool prev = d2 < md[w-1];
                        bool here = d2 < md[w];
                        float nb = prev ? md[w-1] : (here ? d2 : md[w]);
                        int   nj = prev ? mj[w-1] : (here ? j  : mj[w]);
                        md[w] = nb; mj[w] = nj;
                    }
                    if (d2 < md[0]) { md[0] = d2; mj[0] = j; }
                }
            }
        }
        const int gi = node0 + t;
        const size_t rowbase = ((size_t)b * Ni + gi) * W;
#pragma unroll
        for (int q = 0; q < KNN; q++) {
            int j = mj[q];
            atomicOr(&ADJ[rowbase + (j >> 6)], 1ull << (j & 63));
            atomicOr(&ADJ[((size_t)b * Ni + j) * W + (gi >> 6)], 1ull << (gi & 63));
        }
    }
}

// ---------------- LayerNorm (exact R8 structure) ----------------
__global__ __launch_bounds__(128)
void ln_kernel(const float* __restrict__ X, const float* __restrict__ gg,
               const float* __restrict__ bb, float* __restrict__ out, int ldo)
{
    const size_t node = blockIdx.x;
    const int t = threadIdx.x;
    float v = X[node*HD + t];
    __shared__ float sh[4];
    float s = v;
#pragma unroll
    for (int o = 16; o > 0; o >>= 1) s += __shfl_xor_sync(0xffffffffu, s, o);
    if ((t & 31) == 0) sh[t >> 5] = s;
    __syncthreads();
    float mean = (sh[0]+sh[1]+sh[2]+sh[3]) * (1.f/HD);
    __syncthreads();
    float dd = v - mean;
    float q = dd*dd;
#pragma unroll
    for (int o = 16; o > 0; o >>= 1) q += __shfl_xor_sync(0xffffffffu, q, o);
    if ((t & 31) == 0) sh[t >> 5] = q;
    __syncthreads();
    float var = (sh[0]+sh[1]+sh[2]+sh[3]) * (1.f/HD);
    out[node*(size_t)ldo + t] = dd * rsqrtf(var + LN_EPS) * gg[t] + bb[t];
}

// ---------------- fused neighbor-mean aggregation + degree (bit-identical values) ----------------
__global__ __launch_bounds__(128)
void agg_kernel(float* __restrict__ XM, const unsigned long long* __restrict__ ADJ,
                float* __restrict__ DINV, int Ni, int W)
{
    const int g = blockIdx.x;
    const int t = threadIdx.x;
    const int b = g / Ni;
    const size_t base = (size_t)b*Ni;
    const unsigned long long* row = ADJ + (size_t)g*W;
    float acc = 0.f;
    int dcnt = 0;
    for (int w = 0; w < W; w++) {
        unsigned long long word = row[w];
        dcnt += __popcll(word);
        while (word) {
            int bit = __ffsll((long long)word) - 1;
            word &= word - 1;
            int j = w*64 + bit;
            acc += XM[(base + j)*2*HD + t];
        }
    }
    float fd = (float)dcnt;
    XM[(size_t)g*2*HD + HD + t] = acc * (1.0f / fd);
    if (t == 0) DINV[g] = rsqrtf(fd);
}

// ---------------- Y = x @ Wq (exact R8 structure) ----------------
__global__ void yq_kernel(const float* __restrict__ X, const float* __restrict__ Wq,
                          float* __restrict__ Y, int total)
{
    int g = blockIdx.x*8 + threadIdx.y;
    if (g >= total) return;
    int lane = threadIdx.x;
    float4 xv = *(const float4*)&X[(size_t)g*HD + lane*4];
    float4 wv = *(const float4*)&Wq[lane*4];
    float a = xv.x*wv.x + xv.y*wv.y + xv.z*wv.z + xv.w*wv.w;
#pragma unroll
    for (int o = 16; o > 0; o >>= 1) a += __shfl_xor_sync(0xffffffffu, a, o);
    if (lane == 0) Y[g] = a;
}

// ---------------- SAGPool score (exact R8 structure) ----------------
__global__ void score_kernel(const unsigned long long* __restrict__ ADJ, int W, int Ni, int total,
                             const float* __restrict__ DINV, const float* __restrict__ Y,
                             const float* __restrict__ bqp, float* __restrict__ S)
{
    int g = blockIdx.x*256 + threadIdx.x;
    if (g >= total) return;
    int b = g / Ni;
    size_t base = (size_t)b*Ni;
    const unsigned long long* row = ADJ + (size_t)g*W;
    float acc = 0.f;
    for (int w = 0; w < W; w++) {
        unsigned long long word = row[w];
        while (word) {
            int bit = __ffsll((long long)word) - 1;
            word &= word - 1;
            int j = w*64 + bit;
            acc += DINV[base + j] * Y[base + j];
        }
    }
    S[g] = DINV[g] * acc + bqp[0];
}

// ---------------- bitonic top-k (exact R8 structure) ----------------
__global__ __launch_bounds__(1024)
void topk_kernel(const float* __restrict__ S, int Ni, int kk,
                 int* __restrict__ TOPI, float* __restrict__ TOPV)
{
    __shared__ float sv[NMAX];
    __shared__ int   si[NMAX];
    const int b = blockIdx.x;
    const int tid = threadIdx.x;
    for (int i = tid; i < Ni; i += 1024) { sv[i] = S[(size_t)b*Ni + i]; si[i] = i; }
    __syncthreads();
    for (int k = 2; k <= Ni; k <<= 1) {
        for (int j = k >> 1; j > 0; j >>= 1) {
            for (int i = tid; i < Ni; i += 1024) {
                int l = i ^ j;
                if (l > i) {
                    bool up = ((i & k) == 0);
                    float vi = sv[i], vl = sv[l];
                    int ii = si[i], il = si[l];
                    bool iAfterL = (vi < vl) || (vi == vl && ii > il);
                    bool dosw = up ? iAfterL : !iAfterL;
                    if (dosw) { sv[i] = vl; sv[l] = vi; si[i] = il; si[l] = ii; }
                }
            }
            __syncthreads();
        }
    }
    for (int r = tid; r < kk; r += 1024) {
        TOPI[(size_t)b*kk + r] = si[r];
        TOPV[(size_t)b*kk + r] = sv[r];
    }
}

// ---------------- gather + tanh gate + (optional) next-layer ln1 into XM (bit-identical LN) ----------------
__global__ __launch_bounds__(128)
void gather_kernel(const float* __restrict__ Xo, const float* __restrict__ Co,
                   float* __restrict__ Xn, float* __restrict__ Cn,
                   const int* __restrict__ TOPI, const float* __restrict__ TOPV,
                   int Ni, int kk,
                   const float* __restrict__ lng, const float* __restrict__ lnb,
                   float* __restrict__ lnout)
{
    __shared__ float sh[4];
    const int b = blockIdx.y, r = blockIdx.x, t = threadIdx.x;
    const int src = TOPI[(size_t)b*kk + r];
    const float gte = tanhf(TOPV[(size_t)b*kk + r]);
    const size_t node = (size_t)b*kk + r;
    float v = Xo[((size_t)b*Ni + src)*HD + t] * gte;
    Xn[node*HD + t] = v;
    if (t < 2) Cn[node*2 + t] = Co[((size_t)b*Ni + src)*2 + t];

    if (lng) {
        float s = v;
#pragma unroll
        for (int o = 16; o > 0; o >>= 1) s += __shfl_xor_sync(0xffffffffu, s, o);
        if ((t & 31) == 0) sh[t >> 5] = s;
        __syncthreads();
        float mean = (sh[0]+sh[1]+sh[2]+sh[3]) * (1.f/HD);
        __syncthreads();
        float dd = v - mean;
        float q = dd*dd;
#pragma unroll
        for (int o = 16; o > 0; o >>= 1) q += __shfl_xor_sync(0xffffffffu, q, o);
        if ((t & 31) == 0) sh[t >> 5] = q;
        __syncthreads();
        float var = (sh[0]+sh[1]+sh[2]+sh[3]) * (1.f/HD);
        lnout[node*(size_t)(2*HD) + t] = dd * rsqrtf(var + LN_EPS) * lng[t] + lnb[t];
    }
}

// ---------------- two-phase readout (PICKS path is selection-free) ----------------
__global__ __launch_bounds__(128)
void readout_part(const float* __restrict__ Xp, int kk, float* __restrict__ RPART)
{
    const int c = blockIdx.x;       // chunk 0..7
    const int b = blockIdx.y;
    const int t = threadIdx.x;
    const int rows = kk >> 3;
    const int r0 = c * rows;
    float mx = -3.4e38f, sm = 0.f;
    for (int r = 0; r < rows; r++) {
        float v = Xp[((size_t)b*kk + r0 + r)*HD + t];
        mx = fmaxf(mx, v);
        sm += v;
    }
    RPART[((size_t)b*8 + c)*2*HD + t]      = mx;
    RPART[((size_t)b*8 + c)*2*HD + HD + t] = sm;
}

__global__ __launch_bounds__(128)
void readout_comb(const float* __restrict__ RPART, int kk, float* __restrict__ PICKS)
{
    const int b = blockIdx.x, t = threadIdx.x;
    float mx = -3.4e38f, sm = 0.f;
#pragma unroll
    for (int c = 0; c < 8; c++) {
        mx = fmaxf(mx, RPART[((size_t)b*8 + c)*2*HD + t]);
        sm += RPART[((size_t)b*8 + c)*2*HD + HD + t];
    }
    PICKS[b*2*HD + t]      += mx;
    PICKS[b*2*HD + HD + t] += sm / (float)kk;
}

// ---------------- final MLP ----------------
__global__ __launch_bounds__(256)
void final_kernel(const float* __restrict__ Wf1, const float* __restrict__ bf1,
                  const float* __restrict__ Wf2, const float* __restrict__ bf2,
                  float* __restrict__ out)
{
    __shared__ float f1s[BB*HD];
    const int tid = threadIdx.x;
    for (int o = tid; o < BB*HD; o += 256) {
        int b = o >> 7, c = o & 127;
        float a = bf1[c];
        const float* pr = &d_PICKS[b*2*HD];
        for (int k = 0; k < 2*HD; k++) a += pr[k] * Wf1[k*HD + c];
        f1s[o] = fmaxf(a, 0.f);
    }
    __syncthreads();
    int b = tid >> 5, c = tid & 31;
    float a = bf2[c];
    for (int k = 0; k < HD; k++) a += f1s[b*HD + k] * Wf2[k*32 + c];
    out[b*32 + c] = fmaxf(a, 0.f);
}

// ---------------- host orchestration ----------------
#define GEMM_CALL(R, RS, BN, M, NB, Aa, Bb, bi, sc, sh, re, Co, la, lb, lc, Kd)          \
    do {                                                                                  \
        if ((M) >= 12288)                                                                 \
            gemm128<R,RS,BN><<<dim3((M)/128, (NB)), 256>>>(Aa, Bb, bi, sc, sh, re, Co,    \
                                                           la, lb, lc, Kd);               \
        else                                                                              \
            gemm64<R,RS,BN><<<dim3((M)/64, (NB)), 128>>>(Aa, Bb, bi, sc, sh, re, Co,      \
                                                         la, lb, lc, Kd);                 \
    } while (0)

extern "C" void kernel_launch(void* const* d_in, const int* in_sizes, int n_in,
                              void* d_out, int out_size)
{
    const float* feats = (const float*)d_in[0];
    const float* cent  = (const float*)d_in[1];
    const float* Wp1   = (const float*)d_in[2];
    const float* bp1   = (const float*)d_in[3];
    const float* bn_g  = (const float*)d_in[4];
    const float* bn_b  = (const float*)d_in[5];
    const float* Wp2   = (const float*)d_in[6];
    const float* bp2   = (const float*)d_in[7];
    const float* g1    = (const float*)d_in[8];
    const float* be1   = (const float*)d_in[9];
    const float* g2    = (const float*)d_in[10];
    const float* be2   = (const float*)d_in[11];
    const float* Ws    = (const float*)d_in[12];
    const float* Wn    = (const float*)d_in[13];
    const float* bs    = (const float*)d_in[14];
    const float* Wg    = (const float*)d_in[15];
    const float* bg    = (const float*)d_in[16];
    const float* W1    = (const float*)d_in[17];
    const float* b1    = (const float*)d_in[18];
    const float* W2    = (const float*)d_in[19];
    const float* b2    = (const float*)d_in[20];
    const float* Wq    = (const float*)d_in[21];
    const float* bq    = (const float*)d_in[22];
    const float* Wf1   = (const float*)d_in[23];
    const float* bf1   = (const float*)d_in[24];
    const float* Wf2   = (const float*)d_in[25];
    const float* bf2   = (const float*)d_in[26];

    float *Xa, *Xb, *XM, *XN, *T1, *Hb, *Ca, *Cb, *DINV, *Y, *S, *TOPV, *PICKS, *RPART;
    float *WCAT, *BSCAT;
    int* TOPI;
    unsigned long long* ADJ;
    cudaGetSymbolAddress((void**)&Xa, d_X);
    cudaGetSymbolAddress((void**)&Xb, d_XG);
    cudaGetSymbolAddress((void**)&XM, d_XM);
    cudaGetSymbolAddress((void**)&XN, d_XN);
    cudaGetSymbolAddress((void**)&T1, d_T1);
    cudaGetSymbolAddress((void**)&Hb, d_H);
    cudaGetSymbolAddress((void**)&Ca, d_C);
    cudaGetSymbolAddress((void**)&Cb, d_CG);
    cudaGetSymbolAddress((void**)&WCAT, d_WCAT);
    cudaGetSymbolAddress((void**)&BSCAT, d_BSCAT);
    cudaGetSymbolAddress((void**)&ADJ, d_ADJ);
    cudaGetSymbolAddress((void**)&DINV, d_DINV);
    cudaGetSymbolAddress((void**)&Y,  d_Y);
    cudaGetSymbolAddress((void**)&S,  d_S);
    cudaGetSymbolAddress((void**)&TOPI, d_TOPI);
    cudaGetSymbolAddress((void**)&TOPV, d_TOPV);
    cudaGetSymbolAddress((void**)&PICKS, d_PICKS);
    cudaGetSymbolAddress((void**)&RPART, d_RPART);

    const int M0 = MAXNODES;   // 16384 rows

    // weight concat prep
    prep_kernel<<<(NLAYERS*256*512 + 255)/256, 256>>>(Ws, Wn, bs);

    // preconv: T1 = relu(bn(feats@Wp1+bp1)); X = T1@Wp2 + bp2
    GEMM_CALL(true, false, true, M0, 1,
              feats, Wp1, bp1, bn_g, bn_b, nullptr, T1, 512, 128, 128, 512);
    GEMM_CALL(false, false, false, M0, 1,
              T1, Wp2, bp2, nullptr, nullptr, nullptr, Xa, 128, 128, 128, 128);

    cudaMemcpyAsync(Ca, cent, (size_t)M0*2*sizeof(float), cudaMemcpyDeviceToDevice);
    cudaMemsetAsync(PICKS, 0, BB*2*HD*sizeof(float));

    // layer-0 ln1 -> XM[:, :128]
    ln_kernel<<<M0, 128>>>(Xa, g1, be1, XM, 2*HD);

    float *Xcur = Xa, *Xnext = Xb, *Ccur = Ca, *Cnext = Cb;
    int Ni = NMAX;
    for (int i = 0; i < NLAYERS; i++) {
        const int W = Ni / 64;
        const int total = BB * Ni;
        const int kk = Ni / 2;

        cudaMemsetAsync(ADJ, 0, (size_t)total * W * sizeof(unsigned long long));
        knn_kernel<<<dim3(Ni/64, BB), 256>>>(Ccur, Ni, W, ADJ);

        // fused agg + degree (XM[:, :128] holds ln1 already)
        agg_kernel<<<total, 128>>>(XM, ADJ, DINV, Ni, W);

        // fused 4-head GEMM: Hb = relu([XN|Mg] @ WCAT + BSCAT)   [total x 512]
        GEMM_CALL(true, false, false, total, 4,
                  XM, WCAT + (size_t)i*256*512, BSCAT + (size_t)i*512,
                  nullptr, nullptr, nullptr, Hb, 256, 512, 512, 256);
        // out-proj + residual: X += Hb @ Wg + bg
        GEMM_CALL(false, true, false, total, 1,
                  Hb, Wg + (size_t)i*NHEADS*HD*HD, bg + i*HD,
                  nullptr, nullptr, Xcur, Xcur, 512, 128, 128, 512);

        // FFN
        ln_kernel<<<total, 128>>>(Xcur, g2 + i*HD, be2 + i*HD, XN, HD);
        GEMM_CALL(true, false, false, total, 1,
                  XN, W1 + (size_t)i*HD*HD, b1 + i*HD,
                  nullptr, nullptr, nullptr, T1, 128, 128, 128, 128);
        GEMM_CALL(false, true, false, total, 1,
                  T1, W2 + (size_t)i*HD*HD, b2 + i*HD,
                  nullptr, nullptr, Xcur, Xcur, 128, 128, 128, 128);

        // SAGPool
        yq_kernel<<<(total+7)/8, dim3(32, 8)>>>(Xcur, Wq + (size_t)i*HD, Y, total);
        score_kernel<<<(total+255)/256, 256>>>(ADJ, W, Ni, total, DINV, Y, bq + i, S);
        topk_kernel<<<BB, 1024>>>(S, Ni, kk, TOPI, TOPV);
        if (i + 1 < NLAYERS)
            gather_kernel<<<dim3(kk, BB), 128>>>(Xcur, Ccur, Xnext, Cnext, TOPI, TOPV,
                                                 Ni, kk, g1 + (i+1)*HD, be1 + (i+1)*HD, XM);
        else
            gather_kernel<<<dim3(kk, BB), 128>>>(Xcur, Ccur, Xnext, Cnext, TOPI, TOPV,
                                                 Ni, kk, nullptr, nullptr, nullptr);
        readout_part<<<dim3(8, BB), 128>>>(Xnext, kk, RPART);
        readout_comb<<<BB, 128>>>(RPART, kk, PICKS);

        // ping-pong
        float* t;
        t = Xcur; Xcur = Xnext; Xnext = t;
        t = Ccur; Ccur = Cnext; Cnext = t;
        Ni = kk;
    }

    final_kernel<<<1, 256>>>(Wf1, bf1, Wf2, bf2, (float*)d_out);
}

// round 14
// speedup vs baseline: 1.0738x; 1.0143x over previous
#include <cuda_runtime.h>
#include <math.h>

#define BB 8
#define NMAX 2048
#define HD 128
#define NHEADS 4
#define NLAYERS 3
#define KNN 8
#define MAXNODES (BB*NMAX)
#define LN_EPS 1e-5f

// ---------------- device scratch ----------------
__device__ __align__(256) float d_X [MAXNODES*HD];      // ping
__device__ __align__(256) float d_XG[MAXNODES*HD];      // pong
__device__ __align__(256) float d_XM[MAXNODES*2*HD];    // [XN | Mg] concat, stride 256
__device__ __align__(256) float d_XN[MAXNODES*HD];      // ln2 output
__device__ __align__(256) float d_T1[MAXNODES*HD];
__device__ __align__(256) float d_H [MAXNODES*NHEADS*HD];
__device__ __align__(256) float d_C [MAXNODES*2];
__device__ __align__(256) float d_CG[MAXNODES*2];
__device__ __align__(256) float d_WCAT[NLAYERS*256*512];
__device__ __align__(256) float d_BSCAT[NLAYERS*512];
__device__ unsigned long long d_ADJ[(size_t)MAXNODES*(NMAX/64)];
__device__ float d_DINV[MAXNODES];
__device__ float d_Y  [MAXNODES];
__device__ float d_S  [MAXNODES];
__device__ int   d_TOPI[BB*(NMAX/2)];
__device__ float d_TOPV[BB*(NMAX/2)];
__device__ float d_PICKS[BB*2*HD];
__device__ float d_RPART[BB*8*2*HD];

// ---------------- f32x2 helpers ----------------
__device__ __forceinline__ unsigned long long ffma2(unsigned long long a,
                                                    unsigned long long b,
                                                    unsigned long long c) {
    unsigned long long d;
    asm("fma.rn.f32x2 %0, %1, %2, %3;" : "=l"(d) : "l"(a), "l"(b), "l"(c));
    return d;
}
__device__ __forceinline__ unsigned long long dup2(float a) {
    unsigned long long d; unsigned int u = __float_as_uint(a);
    asm("mov.b64 %0, {%1, %1};" : "=l"(d) : "r"(u));
    return d;
}
__device__ __forceinline__ void unpack2(unsigned long long v, float& lo, float& hi) {
    unsigned int l, h;
    asm("mov.b64 {%0, %1}, %2;" : "=r"(l), "=r"(h) : "l"(v));
    lo = __uint_as_float(l); hi = __uint_as_float(h);
}

// ---------------- 128x128 tiled fp32 GEMM ----------------
template<bool RELU, bool HAS_RESID, bool HAS_BN>
__global__ __launch_bounds__(256, 2)
void gemm128(const float* __restrict__ A, const float* __restrict__ Bm,
             const float* __restrict__ bias,
             const float* __restrict__ scale, const float* __restrict__ shift,
             const float* __restrict__ resid, float* __restrict__ Cout,
             int lda, int ldb, int ldc, int Kd)
{
    __shared__ float As[16][128];
    __shared__ float Bs[16][128];
    const int tid = threadIdx.x;
    const int tx = tid & 15, ty = tid >> 4;
    const int row0 = blockIdx.x * 128, col0 = blockIdx.y * 128;

    const int f0 = tid * 2, f1 = tid * 2 + 1;
    const int ar0 = f0 >> 2, ak0 = (f0 & 3) * 4;
    const int ar1 = f1 >> 2, ak1 = (f1 & 3) * 4;
    const int bk0 = f0 >> 5, bc0 = (f0 & 31) * 4;
    const int bk1 = f1 >> 5, bc1 = (f1 & 31) * 4;

    const float* Ar0 = A + (size_t)(row0 + ar0) * lda;
    const float* Ar1 = A + (size_t)(row0 + ar1) * lda;
    const float* Bp  = Bm + col0;

    unsigned long long acc[8][4];
#pragma unroll
    for (int i = 0; i < 8; i++)
#pragma unroll
        for (int j = 0; j < 4; j++) acc[i][j] = 0ull;

    float4 pa0 = *(const float4*)(Ar0 + ak0);
    float4 pa1 = *(const float4*)(Ar1 + ak1);
    float4 pb0 = *(const float4*)(Bp + (size_t)bk0 * ldb + bc0);
    float4 pb1 = *(const float4*)(Bp + (size_t)bk1 * ldb + bc1);

    for (int k0 = 0; k0 < Kd; k0 += 16) {
        As[ak0+0][ar0] = pa0.x; As[ak0+1][ar0] = pa0.y;
        As[ak0+2][ar0] = pa0.z; As[ak0+3][ar0] = pa0.w;
        As[ak1+0][ar1] = pa1.x; As[ak1+1][ar1] = pa1.y;
        As[ak1+2][ar1] = pa1.z; As[ak1+3][ar1] = pa1.w;
        *(float4*)&Bs[bk0][bc0] = pb0;
        *(float4*)&Bs[bk1][bc1] = pb1;
        __syncthreads();
        if (k0 + 16 < Kd) {
            pa0 = *(const float4*)(Ar0 + k0 + 16 + ak0);
            pa1 = *(const float4*)(Ar1 + k0 + 16 + ak1);
            pb0 = *(const float4*)(Bp + (size_t)(k0 + 16 + bk0) * ldb + bc0);
            pb1 = *(const float4*)(Bp + (size_t)(k0 + 16 + bk1) * ldb + bc1);
        }
#pragma unroll
        for (int kk = 0; kk < 16; kk++) {
            float4 a0 = *(const float4*)&As[kk][ty*8];
            float4 a1 = *(const float4*)&As[kk][ty*8+4];
            ulonglong2 p0 = *(const ulonglong2*)&Bs[kk][tx*8];
            ulonglong2 p1 = *(const ulonglong2*)&Bs[kk][tx*8 + 4];
            unsigned long long b2[4] = {p0.x, p0.y, p1.x, p1.y};
            unsigned long long a2;
            a2 = dup2(a0.x);
#pragma unroll
            for (int j = 0; j < 4; j++) acc[0][j] = ffma2(a2, b2[j], acc[0][j]);
            a2 = dup2(a0.y);
#pragma unroll
            for (int j = 0; j < 4; j++) acc[1][j] = ffma2(a2, b2[j], acc[1][j]);
            a2 = dup2(a0.z);
#pragma unroll
            for (int j = 0; j < 4; j++) acc[2][j] = ffma2(a2, b2[j], acc[2][j]);
            a2 = dup2(a0.w);
#pragma unroll
            for (int j = 0; j < 4; j++) acc[3][j] = ffma2(a2, b2[j], acc[3][j]);
            a2 = dup2(a1.x);
#pragma unroll
            for (int j = 0; j < 4; j++) acc[4][j] = ffma2(a2, b2[j], acc[4][j]);
            a2 = dup2(a1.y);
#pragma unroll
            for (int j = 0; j < 4; j++) acc[5][j] = ffma2(a2, b2[j], acc[5][j]);
            a2 = dup2(a1.z);
#pragma unroll
            for (int j = 0; j < 4; j++) acc[6][j] = ffma2(a2, b2[j], acc[6][j]);
            a2 = dup2(a1.w);
#pragma unroll
            for (int j = 0; j < 4; j++) acc[7][j] = ffma2(a2, b2[j], acc[7][j]);
        }
        __syncthreads();
    }

    const float bnf = rsqrtf(1.0f + LN_EPS);
    const int c0 = col0 + tx * 8;
    float bias8[8], sc8[8], sh8[8];
#pragma unroll
    for (int j = 0; j < 8; j++) bias8[j] = bias[c0 + j];
    if (HAS_BN) {
#pragma unroll
        for (int j = 0; j < 8; j++) { sc8[j] = scale[c0 + j] * bnf; sh8[j] = shift[c0 + j]; }
    }
#pragma unroll
    for (int i = 0; i < 8; i++) {
        const int r = row0 + ty * 8 + i;
        float out[8];
#pragma unroll
        for (int j = 0; j < 4; j++) unpack2(acc[i][j], out[2*j], out[2*j+1]);
#pragma unroll
        for (int j = 0; j < 8; j++) {
            float v = out[j] + bias8[j];
            if (HAS_BN) v = v * sc8[j] + sh8[j];
            if (RELU)   v = fmaxf(v, 0.f);
            out[j] = v;
        }
        if (HAS_RESID) {
            float4 r0 = *(const float4*)&resid[(size_t)r*ldc + c0];
            float4 r1 = *(const float4*)&resid[(size_t)r*ldc + c0 + 4];
            out[0]+=r0.x; out[1]+=r0.y; out[2]+=r0.z; out[3]+=r0.w;
            out[4]+=r1.x; out[5]+=r1.y; out[6]+=r1.z; out[7]+=r1.w;
        }
        *(float4*)&Cout[(size_t)r*ldc + c0]     = make_float4(out[0],out[1],out[2],out[3]);
        *(float4*)&Cout[(size_t)r*ldc + c0 + 4] = make_float4(out[4],out[5],out[6],out[7]);
    }
}

// ---------------- 64x128 tile variant (bit-identical arithmetic) ----------------
template<bool RELU, bool HAS_RESID, bool HAS_BN>
__global__ __launch_bounds__(128, 4)
void gemm64(const float* __restrict__ A, const float* __restrict__ Bm,
            const float* __restrict__ bias,
            const float* __restrict__ scale, const float* __restrict__ shift,
            const float* __restrict__ resid, float* __restrict__ Cout,
            int lda, int ldb, int ldc, int Kd)
{
    __shared__ float As[16][64];
    __shared__ float Bs[16][128];
    const int tid = threadIdx.x;
    const int tx = tid & 15, ty = tid >> 4;
    const int row0 = blockIdx.x * 64, col0 = blockIdx.y * 128;

    const int f0 = tid * 2, f1 = tid * 2 + 1;
    const int ar0 = f0 >> 2, ak0 = (f0 & 3) * 4;
    const int ar1 = f1 >> 2, ak1 = (f1 & 3) * 4;
    const int g0 = tid * 4;
    const int bk0 = g0 >> 5,       bc0 = (g0 & 31) * 4;
    const int bk1 = (g0+1) >> 5,   bc1 = ((g0+1) & 31) * 4;
    const int bk2 = (g0+2) >> 5,   bc2 = ((g0+2) & 31) * 4;
    const int bk3 = (g0+3) >> 5,   bc3 = ((g0+3) & 31) * 4;

    const float* Ar0 = A + (size_t)(row0 + ar0) * lda;
    const float* Ar1 = A + (size_t)(row0 + ar1) * lda;
    const float* Bp  = Bm + col0;

    unsigned long long acc[8][4];
#pragma unroll
    for (int i = 0; i < 8; i++)
#pragma unroll
        for (int j = 0; j < 4; j++) acc[i][j] = 0ull;

    float4 pa0 = *(const float4*)(Ar0 + ak0);
    float4 pa1 = *(const float4*)(Ar1 + ak1);
    float4 pb0 = *(const float4*)(Bp + (size_t)bk0 * ldb + bc0);
    float4 pb1 = *(const float4*)(Bp + (size_t)bk1 * ldb + bc1);
    float4 pb2 = *(const float4*)(Bp + (size_t)bk2 * ldb + bc2);
    float4 pb3 = *(const float4*)(Bp + (size_t)bk3 * ldb + bc3);

    for (int k0 = 0; k0 < Kd; k0 += 16) {
        As[ak0+0][ar0] = pa0.x; As[ak0+1][ar0] = pa0.y;
        As[ak0+2][ar0] = pa0.z; As[ak0+3][ar0] = pa0.w;
        As[ak1+0][ar1] = pa1.x; As[ak1+1][ar1] = pa1.y;
        As[ak1+2][ar1] = pa1.z; As[ak1+3][ar1] = pa1.w;
        *(float4*)&Bs[bk0][bc0] = pb0;
        *(float4*)&Bs[bk1][bc1] = pb1;
        *(float4*)&Bs[bk2][bc2] = pb2;
        *(float4*)&Bs[bk3][bc3] = pb3;
        __syncthreads();
        if (k0 + 16 < Kd) {
            pa0 = *(const float4*)(Ar0 + k0 + 16 + ak0);
            pa1 = *(const float4*)(Ar1 + k0 + 16 + ak1);
            pb0 = *(const float4*)(Bp + (size_t)(k0 + 16 + bk0) * ldb + bc0);
            pb1 = *(const float4*)(Bp + (size_t)(k0 + 16 + bk1) * ldb + bc1);
            pb2 = *(const float4*)(Bp + (size_t)(k0 + 16 + bk2) * ldb + bc2);
            pb3 = *(const float4*)(Bp + (size_t)(k0 + 16 + bk3) * ldb + bc3);
        }
#pragma unroll
        for (int kk = 0; kk < 16; kk++) {
            float4 a0 = *(const float4*)&As[kk][ty*8];
            float4 a1 = *(const float4*)&As[kk][ty*8+4];
            ulonglong2 p0 = *(const ulonglong2*)&Bs[kk][tx*8];
            ulonglong2 p1 = *(const ulonglong2*)&Bs[kk][tx*8 + 4];
            unsigned long long b2[4] = {p0.x, p0.y, p1.x, p1.y};
            unsigned long long a2;
            a2 = dup2(a0.x);
#pragma unroll
            for (int j = 0; j < 4; j++) acc[0][j] = ffma2(a2, b2[j], acc[0][j]);
            a2 = dup2(a0.y);
#pragma unroll
            for (int j = 0; j < 4; j++) acc[1][j] = ffma2(a2, b2[j], acc[1][j]);
            a2 = dup2(a0.z);
#pragma unroll
            for (int j = 0; j < 4; j++) acc[2][j] = ffma2(a2, b2[j], acc[2][j]);
            a2 = dup2(a0.w);
#pragma unroll
            for (int j = 0; j < 4; j++) acc[3][j] = ffma2(a2, b2[j], acc[3][j]);
            a2 = dup2(a1.x);
#pragma unroll
            for (int j = 0; j < 4; j++) acc[4][j] = ffma2(a2, b2[j], acc[4][j]);
            a2 = dup2(a1.y);
#pragma unroll
            for (int j = 0; j < 4; j++) acc[5][j] = ffma2(a2, b2[j], acc[5][j]);
            a2 = dup2(a1.z);
#pragma unroll
            for (int j = 0; j < 4; j++) acc[6][j] = ffma2(a2, b2[j], acc[6][j]);
            a2 = dup2(a1.w);
#pragma unroll
            for (int j = 0; j < 4; j++) acc[7][j] = ffma2(a2, b2[j], acc[7][j]);
        }
        __syncthreads();
    }

    const float bnf = rsqrtf(1.0f + LN_EPS);
    const int c0 = col0 + tx * 8;
    float bias8[8], sc8[8], sh8[8];
#pragma unroll
    for (int j = 0; j < 8; j++) bias8[j] = bias[c0 + j];
    if (HAS_BN) {
#pragma unroll
        for (int j = 0; j < 8; j++) { sc8[j] = scale[c0 + j] * bnf; sh8[j] = shift[c0 + j]; }
    }
#pragma unroll
    for (int i = 0; i < 8; i++) {
        const int r = row0 + ty * 8 + i;
        float out[8];
#pragma unroll
        for (int j = 0; j < 4; j++) unpack2(acc[i][j], out[2*j], out[2*j+1]);
#pragma unroll
        for (int j = 0; j < 8; j++) {
            float v = out[j] + bias8[j];
            if (HAS_BN) v = v * sc8[j] + sh8[j];
            if (RELU)   v = fmaxf(v, 0.f);
            out[j] = v;
        }
        if (HAS_RESID) {
            float4 r0 = *(const float4*)&resid[(size_t)r*ldc + c0];
            float4 r1 = *(const float4*)&resid[(size_t)r*ldc + c0 + 4];
            out[0]+=r0.x; out[1]+=r0.y; out[2]+=r0.z; out[3]+=r0.w;
            out[4]+=r1.x; out[5]+=r1.y; out[6]+=r1.z; out[7]+=r1.w;
        }
        *(float4*)&Cout[(size_t)r*ldc + c0]     = make_float4(out[0],out[1],out[2],out[3]);
        *(float4*)&Cout[(size_t)r*ldc + c0 + 4] = make_float4(out[4],out[5],out[6],out[7]);
    }
}

// ---------------- weight concat prep ----------------
__global__ void prep_kernel(const float* __restrict__ Ws, const float* __restrict__ Wn,
                            const float* __restrict__ bs)
{
    int idx = blockIdx.x * 256 + threadIdx.x;
    if (idx < NLAYERS * 256 * 512) {
        int i = idx / (256 * 512);
        int rem = idx % (256 * 512);
        int d = rem / 512, col = rem % 512;
        int h = col >> 7, e = col & 127;
        const float* src = (d < 128) ? Ws : Wn;
        d_WCAT[idx] = src[((((size_t)i * NHEADS) + h) * HD + (d & 127)) * HD + e];
    }
    if (idx < NLAYERS * 512) {
        int i = idx / 512, col = idx % 512;
        d_BSCAT[idx] = bs[(i * NHEADS + (col >> 7)) * HD + (col & 127)];
    }
}

// ---------------- KNN: 64 nodes x 4 j-partitions, j-loop unrolled x2 (bit-identical ADJ) ----------------
__global__ __launch_bounds__(256)
void knn_kernel(const float* __restrict__ C, int Ni, int W,
                unsigned long long* __restrict__ ADJ)
{
    __shared__ float2 sc[NMAX];
    __shared__ float sd[64 * 4 * KNN];
    __shared__ int   sj[64 * 4 * KNN];
    const int b = blockIdx.y;
    const int node0 = blockIdx.x * 64;
    const int t = threadIdx.x;
    const int nl = t & 63, part = t >> 6;
    const float2* cb = (const float2*)(C + (size_t)b * Ni * 2);
    for (int idx = t; idx < Ni; idx += 256) sc[idx] = cb[idx];
    __syncthreads();

    const int i = node0 + nl;
    const float2 me = sc[i];
    float bd[KNN]; int bj[KNN];
#pragma unroll
    for (int q = 0; q < KNN; q++) { bd[q] = 3.4e38f; bj[q] = 0x7fffffff; }

    auto try_insert = [&](float d2, int j) {
        if (d2 < bd[KNN-1]) {
#pragma unroll
            for (int q = KNN-1; q > 0; --q) {
                bool prev = d2 < bd[q-1];
                bool here = d2 < bd[q];
                float nb = prev ? bd[q-1] : (here ? d2 : bd[q]);
                int   nj = prev ? bj[q-1] : (here ? j  : bj[q]);
                bd[q] = nb; bj[q] = nj;
            }
            if (d2 < bd[0]) { bd[0] = d2; bj[0] = j; }
        }
    };

    const int jlen = Ni >> 2;
    const int j0 = part * jlen;
    for (int jj = 0; jj < jlen; jj += 2) {
        int j = j0 + jj;
        float4 p = *(const float4*)(&sc[j]);
        float dx0 = me.x - p.x, dy0 = me.y - p.y;
        float d20 = dx0 * dx0 + dy0 * dy0;
        float dx1 = me.x - p.z, dy1 = me.y - p.w;
        float d21 = dx1 * dx1 + dy1 * dy1;
        try_insert(d20, j);
        try_insert(d21, j + 1);
    }
#pragma unroll
    for (int q = 0; q < KNN; q++) {
        sd[(nl * 4 + part) * KNN + q] = bd[q];
        sj[(nl * 4 + part) * KNN + q] = bj[q];
    }
    __syncthreads();

    if (t < 64) {
        float md[KNN]; int mj[KNN];
#pragma unroll
        for (int q = 0; q < KNN; q++) { md[q] = 3.4e38f; mj[q] = 0x7fffffff; }
        for (int p = 0; p < 4; p++) {
#pragma unroll
            for (int q = 0; q < KNN; q++) {
                float d2 = sd[(t * 4 + p) * KNN + q];
                int   j  = sj[(t * 4 + p) * KNN + q];
                if (d2 < md[KNN-1]) {
#pragma unroll
                    for (int w = KNN-1; w > 0; --w) {
                        bool prev = d2 < md[w-1];
                        bool here = d2 < md[w];
                        float nb = prev ? md[w-1] : (here ? d2 : md[w]);
                        int   nj = prev ? mj[w-1] : (here ? j  : mj[w]);
                        md[w] = nb; mj[w] = nj;
                    }
                    if (d2 < md[0]) { md[0] = d2; mj[0] = j; }
                }
            }
        }
        const int gi = node0 + t;
        const size_t rowbase = ((size_t)b * Ni + gi) * W;
#pragma unroll
        for (int q = 0; q < KNN; q++) {
            int j = mj[q];
            atomicOr(&ADJ[rowbase + (j >> 6)], 1ull << (j & 63));
            atomicOr(&ADJ[((size_t)b * Ni + j) * W + (gi >> 6)], 1ull << (gi & 63));
        }
    }
}

// ---------------- LayerNorm: 4 nodes per 512-thread block (per-node reduction bit-identical) ----------------
__global__ __launch_bounds__(512)
void ln_kernel(const float* __restrict__ X, const float* __restrict__ gg,
               const float* __restrict__ bb, float* __restrict__ out, int ldo)
{
    __shared__ float sh[16];
    const size_t node = (size_t)blockIdx.x * 4 + (threadIdx.x >> 7);
    const int t = threadIdx.x & 127;
    const int nslot = (threadIdx.x >> 7) * 4;
    float v = X[node*HD + t];
    float s = v;
#pragma unroll
    for (int o = 16; o > 0; o >>= 1) s += __shfl_xor_sync(0xffffffffu, s, o);
    if ((t & 31) == 0) sh[nslot + (t >> 5)] = s;
    __syncthreads();
    float mean = (sh[nslot]+sh[nslot+1]+sh[nslot+2]+sh[nslot+3]) * (1.f/HD);
    __syncthreads();
    float dd = v - mean;
    float q = dd*dd;
#pragma unroll
    for (int o = 16; o > 0; o >>= 1) q += __shfl_xor_sync(0xffffffffu, q, o);
    if ((t & 31) == 0) sh[nslot + (t >> 5)] = q;
    __syncthreads();
    float var = (sh[nslot]+sh[nslot+1]+sh[nslot+2]+sh[nslot+3]) * (1.f/HD);
    out[node*(size_t)ldo + t] = dd * rsqrtf(var + LN_EPS) * gg[t] + bb[t];
}

// ---------------- fused neighbor-mean aggregation + degree ----------------
__global__ __launch_bounds__(128)
void agg_kernel(float* __restrict__ XM, const unsigned long long* __restrict__ ADJ,
                float* __restrict__ DINV, int Ni, int W)
{
    const int g = blockIdx.x;
    const int t = threadIdx.x;
    const int b = g / Ni;
    const size_t base = (size_t)b*Ni;
    const unsigned long long* row = ADJ + (size_t)g*W;
    float acc = 0.f;
    int dcnt = 0;
    for (int w = 0; w < W; w++) {
        unsigned long long word = row[w];
        dcnt += __popcll(word);
        while (word) {
            int bit = __ffsll((long long)word) - 1;
            word &= word - 1;
            int j = w*64 + bit;
            acc += XM[(base + j)*2*HD + t];
        }
    }
    float fd = (float)dcnt;
    XM[(size_t)g*2*HD + HD + t] = acc * (1.0f / fd);
    if (t == 0) DINV[g] = rsqrtf(fd);
}

// ---------------- Y = x @ Wq ----------------
__global__ void yq_kernel(const float* __restrict__ X, const float* __restrict__ Wq,
                          float* __restrict__ Y, int total)
{
    int g = blockIdx.x*8 + threadIdx.y;
    if (g >= total) return;
    int lane = threadIdx.x;
    float4 xv = *(const float4*)&X[(size_t)g*HD + lane*4];
    float4 wv = *(const float4*)&Wq[lane*4];
    float a = xv.x*wv.x + xv.y*wv.y + xv.z*wv.z + xv.w*wv.w;
#pragma unroll
    for (int o = 16; o > 0; o >>= 1) a += __shfl_xor_sync(0xffffffffu, a, o);
    if (lane == 0) Y[g] = a;
}

// ---------------- SAGPool score ----------------
__global__ void score_kernel(const unsigned long long* __restrict__ ADJ, int W, int Ni, int total,
                             const float* __restrict__ DINV, const float* __restrict__ Y,
                             const float* __restrict__ bqp, float* __restrict__ S)
{
    int g = blockIdx.x*256 + threadIdx.x;
    if (g >= total) return;
    int b = g / Ni;
    size_t base = (size_t)b*Ni;
    const unsigned long long* row = ADJ + (size_t)g*W;
    float acc = 0.f;
    for (int w = 0; w < W; w++) {
        unsigned long long word = row[w];
        while (word) {
            int bit = __ffsll((long long)word) - 1;
            word &= word - 1;
            int j = w*64 + bit;
            acc += DINV[base + j] * Y[base + j];
        }
    }
    S[g] = DINV[g] * acc + bqp[0];
}

// ---------------- bitonic top-k ----------------
__global__ __launch_bounds__(1024)
void topk_kernel(const float* __restrict__ S, int Ni, int kk,
                 int* __restrict__ TOPI, float* __restrict__ TOPV)
{
    __shared__ float sv[NMAX];
    __shared__ int   si[NMAX];
    const int b = blockIdx.x;
    const int tid = threadIdx.x;
    for (int i = tid; i < Ni; i += 1024) { sv[i] = S[(size_t)b*Ni + i]; si[i] = i; }
    __syncthreads();
    for (int k = 2; k <= Ni; k <<= 1) {
        for (int j = k >> 1; j > 0; j >>= 1) {
            for (int i = tid; i < Ni; i += 1024) {
                int l = i ^ j;
                if (l > i) {
                    bool up = ((i & k) == 0);
                    float vi = sv[i], vl = sv[l];
                    int ii = si[i], il = si[l];
                    bool iAfterL = (vi < vl) || (vi == vl && ii > il);
                    bool dosw = up ? iAfterL : !iAfterL;
                    if (dosw) { sv[i] = vl; sv[l] = vi; si[i] = il; si[l] = ii; }
                }
            }
            __syncthreads();
        }
    }
    for (int r = tid; r < kk; r += 1024) {
        TOPI[(size_t)b*kk + r] = si[r];
        TOPV[(size_t)b*kk + r] = sv[r];
    }
}

// ---------------- gather + tanh gate + (optional) next-layer ln1 into XM ----------------
__global__ __launch_bounds__(128)
void gather_kernel(const float* __restrict__ Xo, const float* __restrict__ Co,
                   float* __restrict__ Xn, float* __restrict__ Cn,
                   const int* __restrict__ TOPI, const float* __restrict__ TOPV,
                   int Ni, int kk,
                   const float* __restrict__ lng, const float* __restrict__ lnb,
                   float* __restrict__ lnout)
{
    __shared__ float sh[4];
    const int b = blockIdx.y, r = blockIdx.x, t = threadIdx.x;
    const int src = TOPI[(size_t)b*kk + r];
    const float gte = tanhf(TOPV[(size_t)b*kk + r]);
    const size_t node = (size_t)b*kk + r;
    float v = Xo[((size_t)b*Ni + src)*HD + t] * gte;
    Xn[node*HD + t] = v;
    if (t < 2) Cn[node*2 + t] = Co[((size_t)b*Ni + src)*2 + t];

    if (lng) {
        float s = v;
#pragma unroll
        for (int o = 16; o > 0; o >>= 1) s += __shfl_xor_sync(0xffffffffu, s, o);
        if ((t & 31) == 0) sh[t >> 5] = s;
        __syncthreads();
        float mean = (sh[0]+sh[1]+sh[2]+sh[3]) * (1.f/HD);
        __syncthreads();
        float dd = v - mean;
        float q = dd*dd;
#pragma unroll
        for (int o = 16; o > 0; o >>= 1) q += __shfl_xor_sync(0xffffffffu, q, o);
        if ((t & 31) == 0) sh[t >> 5] = q;
        __syncthreads();
        float var = (sh[0]+sh[1]+sh[2]+sh[3]) * (1.f/HD);
        lnout[node*(size_t)(2*HD) + t] = dd * rsqrtf(var + LN_EPS) * lng[t] + lnb[t];
    }
}

// ---------------- two-phase readout ----------------
__global__ __launch_bounds__(128)
void readout_part(const float* __restrict__ Xp, int kk, float* __restrict__ RPART)
{
    const int c = blockIdx.x;
    const int b = blockIdx.y;
    const int t = threadIdx.x;
    const int rows = kk >> 3;
    const int r0 = c * rows;
    float mx = -3.4e38f, sm = 0.f;
    for (int r = 0; r < rows; r++) {
        float v = Xp[((size_t)b*kk + r0 + r)*HD + t];
        mx = fmaxf(mx, v);
        sm += v;
    }
    RPART[((size_t)b*8 + c)*2*HD + t]      = mx;
    RPART[((size_t)b*8 + c)*2*HD + HD + t] = sm;
}

__global__ __launch_bounds__(128)
void readout_comb(const float* __restrict__ RPART, int kk, float* __restrict__ PICKS)
{
    const int b = blockIdx.x, t = threadIdx.x;
    float mx = -3.4e38f, sm = 0.f;
#pragma unroll
    for (int c = 0; c < 8; c++) {
        mx = fmaxf(mx, RPART[((size_t)b*8 + c)*2*HD + t]);
        sm += RPART[((size_t)b*8 + c)*2*HD + HD + t];
    }
    PICKS[b*2*HD + t]      += mx;
    PICKS[b*2*HD + HD + t] += sm / (float)kk;
}

// ---------------- final MLP ----------------
__global__ __launch_bounds__(256)
void final_kernel(const float* __restrict__ Wf1, const float* __restrict__ bf1,
                  const float* __restrict__ Wf2, const float* __restrict__ bf2,
                  float* __restrict__ out)
{
    __shared__ float f1s[BB*HD];
    const int tid = threadIdx.x;
    for (int o = tid; o < BB*HD; o += 256) {
        int b = o >> 7, c = o & 127;
        float a = bf1[c];
        const float* pr = &d_PICKS[b*2*HD];
        for (int k = 0; k < 2*HD; k++) a += pr[k] * Wf1[k*HD + c];
        f1s[o] = fmaxf(a, 0.f);
    }
    __syncthreads();
    int b = tid >> 5, c = tid & 31;
    float a = bf2[c];
    for (int k = 0; k < HD; k++) a += f1s[b*HD + k] * Wf2[k*32 + c];
    out[b*32 + c] = fmaxf(a, 0.f);
}

// ---------------- host orchestration ----------------
#define GEMM_CALL(R, RS, BN, M, NB, Aa, Bb, bi, sc, sh, re, Co, la, lb, lc, Kd)          \
    do {                                                                                  \
        if ((M) >= 12288)                                                                 \
            gemm128<R,RS,BN><<<dim3((M)/128, (NB)), 256>>>(Aa, Bb, bi, sc, sh, re, Co,    \
                                                           la, lb, lc, Kd);               \
        else                                                                              \
            gemm64<R,RS,BN><<<dim3((M)/64, (NB)), 128>>>(Aa, Bb, bi, sc, sh, re, Co,      \
                                                         la, lb, lc, Kd);                 \
    } while (0)

extern "C" void kernel_launch(void* const* d_in, const int* in_sizes, int n_in,
                              void* d_out, int out_size)
{
    const float* feats = (const float*)d_in[0];
    const float* cent  = (const float*)d_in[1];
    const float* Wp1   = (const float*)d_in[2];
    const float* bp1   = (const float*)d_in[3];
    const float* bn_g  = (const float*)d_in[4];
    const float* bn_b  = (const float*)d_in[5];
    const float* Wp2   = (const float*)d_in[6];
    const float* bp2   = (const float*)d_in[7];
    const float* g1    = (const float*)d_in[8];
    const float* be1   = (const float*)d_in[9];
    const float* g2    = (const float*)d_in[10];
    const float* be2   = (const float*)d_in[11];
    const float* Ws    = (const float*)d_in[12];
    const float* Wn    = (const float*)d_in[13];
    const float* bs    = (const float*)d_in[14];
    const float* Wg    = (const float*)d_in[15];
    const float* bg    = (const float*)d_in[16];
    const float* W1    = (const float*)d_in[17];
    const float* b1    = (const float*)d_in[18];
    const float* W2    = (const float*)d_in[19];
    const float* b2    = (const float*)d_in[20];
    const float* Wq    = (const float*)d_in[21];
    const float* bq    = (const float*)d_in[22];
    const float* Wf1   = (const float*)d_in[23];
    const float* bf1   = (const float*)d_in[24];
    const float* Wf2   = (const float*)d_in[25];
    const float* bf2   = (const float*)d_in[26];

    float *Xa, *Xb, *XM, *XN, *T1, *Hb, *Ca, *Cb, *DINV, *Y, *S, *TOPV, *PICKS, *RPART;
    float *WCAT, *BSCAT;
    int* TOPI;
    unsigned long long* ADJ;
    cudaGetSymbolAddress((void**)&Xa, d_X);
    cudaGetSymbolAddress((void**)&Xb, d_XG);
    cudaGetSymbolAddress((void**)&XM, d_XM);
    cudaGetSymbolAddress((void**)&XN, d_XN);
    cudaGetSymbolAddress((void**)&T1, d_T1);
    cudaGetSymbolAddress((void**)&Hb, d_H);
    cudaGetSymbolAddress((void**)&Ca, d_C);
    cudaGetSymbolAddress((void**)&Cb, d_CG);
    cudaGetSymbolAddress((void**)&WCAT, d_WCAT);
    cudaGetSymbolAddress((void**)&BSCAT, d_BSCAT);
    cudaGetSymbolAddress((void**)&ADJ, d_ADJ);
    cudaGetSymbolAddress((void**)&DINV, d_DINV);
    cudaGetSymbolAddress((void**)&Y,  d_Y);
    cudaGetSymbolAddress((void**)&S,  d_S);
    cudaGetSymbolAddress((void**)&TOPI, d_TOPI);
    cudaGetSymbolAddress((void**)&TOPV, d_TOPV);
    cudaGetSymbolAddress((void**)&PICKS, d_PICKS);
    cudaGetSymbolAddress((void**)&RPART, d_RPART);

    const int M0 = MAXNODES;   // 16384 rows

    // weight concat prep
    prep_kernel<<<(NLAYERS*256*512 + 255)/256, 256>>>(Ws, Wn, bs);

    // preconv: T1 = relu(bn(feats@Wp1+bp1)); X = T1@Wp2 + bp2
    GEMM_CALL(true, false, true, M0, 1,
              feats, Wp1, bp1, bn_g, bn_b, nullptr, T1, 512, 128, 128, 512);
    GEMM_CALL(false, false, false, M0, 1,
              T1, Wp2, bp2, nullptr, nullptr, nullptr, Xa, 128, 128, 128, 128);

    cudaMemcpyAsync(Ca, cent, (size_t)M0*2*sizeof(float), cudaMemcpyDeviceToDevice);
    cudaMemsetAsync(PICKS, 0, BB*2*HD*sizeof(float));

    // layer-0 ln1 -> XM[:, :128]
    ln_kernel<<<M0/4, 512>>>(Xa, g1, be1, XM, 2*HD);

    float *Xcur = Xa, *Xnext = Xb, *Ccur = Ca, *Cnext = Cb;
    int Ni = NMAX;
    for (int i = 0; i < NLAYERS; i++) {
        const int W = Ni / 64;
        const int total = BB * Ni;
        const int kk = Ni / 2;

        cudaMemsetAsync(ADJ, 0, (size_t)total * W * sizeof(unsigned long long));
        knn_kernel<<<dim3(Ni/64, BB), 256>>>(Ccur, Ni, W, ADJ);

        // fused agg + degree (XM[:, :128] holds ln1 already)
        agg_kernel<<<total, 128>>>(XM, ADJ, DINV, Ni, W);

        // fused 4-head GEMM: Hb = relu([XN|Mg] @ WCAT + BSCAT)   [total x 512]
        GEMM_CALL(true, false, false, total, 4,
                  XM, WCAT + (size_t)i*256*512, BSCAT + (size_t)i*512,
                  nullptr, nullptr, nullptr, Hb, 256, 512, 512, 256);
        // out-proj + residual: X += Hb @ Wg + bg
        GEMM_CALL(false, true, false, total, 1,
                  Hb, Wg + (size_t)i*NHEADS*HD*HD, bg + i*HD,
                  nullptr, nullptr, Xcur, Xcur, 512, 128, 128, 512);

        // FFN
        ln_kernel<<<total/4, 512>>>(Xcur, g2 + i*HD, be2 + i*HD, XN, HD);
        GEMM_CALL(true, false, false, total, 1,
                  XN, W1 + (size_t)i*HD*HD, b1 + i*HD,
                  nullptr, nullptr, nullptr, T1, 128, 128, 128, 128);
        GEMM_CALL(false, true, false, total, 1,
                  T1, W2 + (size_t)i*HD*HD, b2 + i*HD,
                  nullptr, nullptr, Xcur, Xcur, 128, 128, 128, 128);

        // SAGPool
        yq_kernel<<<(total+7)/8, dim3(32, 8)>>>(Xcur, Wq + (size_t)i*HD, Y, total);
        score_kernel<<<(total+255)/256, 256>>>(ADJ, W, Ni, total, DINV, Y, bq + i, S);
        topk_kernel<<<BB, 1024>>>(S, Ni, kk, TOPI, TOPV);
        if (i + 1 < NLAYERS)
            gather_kernel<<<dim3(kk, BB), 128>>>(Xcur, Ccur, Xnext, Cnext, TOPI, TOPV,
                                                 Ni, kk, g1 + (i+1)*HD, be1 + (i+1)*HD, XM);
        else
            gather_kernel<<<dim3(kk, BB), 128>>>(Xcur, Ccur, Xnext, Cnext, TOPI, TOPV,
                                                 Ni, kk, nullptr, nullptr, nullptr);
        readout_part<<<dim3(8, BB), 128>>>(Xnext, kk, RPART);
        readout_comb<<<BB, 128>>>(RPART, kk, PICKS);

        // ping-pong
        float* t;
        t = Xcur; Xcur = Xnext; Xnext = t;
        t = Ccur; Ccur = Cnext; Cnext = t;
        Ni = kk;
    }

    final_kernel<<<1, 256>>>(Wf1, bf1, Wf2, bf2, (float*)d_out);
}

// round 15
// speedup vs baseline: 1.0789x; 1.0047x over previous
#include <cuda_runtime.h>
#include <math.h>

#define BB 8
#define NMAX 2048
#define HD 128
#define NHEADS 4
#define NLAYERS 3
#define KNN 8
#define MAXNODES (BB*NMAX)
#define LN_EPS 1e-5f

// ---------------- device scratch ----------------
__device__ __align__(256) float d_X [MAXNODES*HD];      // ping
__device__ __align__(256) float d_XG[MAXNODES*HD];      // pong
__device__ __align__(256) float d_XM[MAXNODES*2*HD];    // [XN | Mg] concat, stride 256
__device__ __align__(256) float d_XN[MAXNODES*HD];      // ln2 output
__device__ __align__(256) float d_T1[MAXNODES*HD];
__device__ __align__(256) float d_H [MAXNODES*NHEADS*HD];
__device__ __align__(256) float d_C [MAXNODES*2];
__device__ __align__(256) float d_CG[MAXNODES*2];
__device__ __align__(256) float d_WCAT[NLAYERS*256*512];
__device__ __align__(256) float d_BSCAT[NLAYERS*512];
__device__ unsigned long long d_ADJ[(size_t)MAXNODES*(NMAX/64)];
__device__ float d_DINV[MAXNODES];
__device__ float d_Y  [MAXNODES];
__device__ float d_S  [MAXNODES];
__device__ int   d_TOPI[BB*(NMAX/2)];
__device__ float d_TOPV[BB*(NMAX/2)];
__device__ float d_PICKS[BB*2*HD];
__device__ float d_RPART[BB*8*2*HD];

// ---------------- f32x2 helpers ----------------
__device__ __forceinline__ unsigned long long ffma2(unsigned long long a,
                                                    unsigned long long b,
                                                    unsigned long long c) {
    unsigned long long d;
    asm("fma.rn.f32x2 %0, %1, %2, %3;" : "=l"(d) : "l"(a), "l"(b), "l"(c));
    return d;
}
__device__ __forceinline__ unsigned long long dup2(float a) {
    unsigned long long d; unsigned int u = __float_as_uint(a);
    asm("mov.b64 %0, {%1, %1};" : "=l"(d) : "r"(u));
    return d;
}
__device__ __forceinline__ void unpack2(unsigned long long v, float& lo, float& hi) {
    unsigned int l, h;
    asm("mov.b64 {%0, %1}, %2;" : "=r"(l), "=r"(h) : "l"(v));
    lo = __uint_as_float(l); hi = __uint_as_float(h);
}

// ---------------- 128x128 tiled fp32 GEMM, double-buffered smem ----------------
template<bool RELU, bool HAS_RESID, bool HAS_BN>
__global__ __launch_bounds__(256, 2)
void gemm128(const float* __restrict__ A, const float* __restrict__ Bm,
             const float* __restrict__ bias,
             const float* __restrict__ scale, const float* __restrict__ shift,
             const float* __restrict__ resid, float* __restrict__ Cout,
             int lda, int ldb, int ldc, int Kd)
{
    __shared__ float As[2][16][128];
    __shared__ float Bs[2][16][128];
    const int tid = threadIdx.x;
    const int tx = tid & 15, ty = tid >> 4;
    const int row0 = blockIdx.x * 128, col0 = blockIdx.y * 128;

    const int f0 = tid * 2, f1 = tid * 2 + 1;
    const int ar0 = f0 >> 2, ak0 = (f0 & 3) * 4;
    const int ar1 = f1 >> 2, ak1 = (f1 & 3) * 4;
    const int bk0 = f0 >> 5, bc0 = (f0 & 31) * 4;
    const int bk1 = f1 >> 5, bc1 = (f1 & 31) * 4;

    const float* Ar0 = A + (size_t)(row0 + ar0) * lda;
    const float* Ar1 = A + (size_t)(row0 + ar1) * lda;
    const float* Bp  = Bm + col0;

    unsigned long long acc[8][4];
#pragma unroll
    for (int i = 0; i < 8; i++)
#pragma unroll
        for (int j = 0; j < 4; j++) acc[i][j] = 0ull;

    float4 pa0 = *(const float4*)(Ar0 + ak0);
    float4 pa1 = *(const float4*)(Ar1 + ak1);
    float4 pb0 = *(const float4*)(Bp + (size_t)bk0 * ldb + bc0);
    float4 pb1 = *(const float4*)(Bp + (size_t)bk1 * ldb + bc1);
    As[0][ak0+0][ar0] = pa0.x; As[0][ak0+1][ar0] = pa0.y;
    As[0][ak0+2][ar0] = pa0.z; As[0][ak0+3][ar0] = pa0.w;
    As[0][ak1+0][ar1] = pa1.x; As[0][ak1+1][ar1] = pa1.y;
    As[0][ak1+2][ar1] = pa1.z; As[0][ak1+3][ar1] = pa1.w;
    *(float4*)&Bs[0][bk0][bc0] = pb0;
    *(float4*)&Bs[0][bk1][bc1] = pb1;
    __syncthreads();

    int buf = 0;
    for (int k0 = 0; k0 < Kd; k0 += 16) {
        const bool has_next = (k0 + 16 < Kd);
        if (has_next) {
            pa0 = *(const float4*)(Ar0 + k0 + 16 + ak0);
            pa1 = *(const float4*)(Ar1 + k0 + 16 + ak1);
            pb0 = *(const float4*)(Bp + (size_t)(k0 + 16 + bk0) * ldb + bc0);
            pb1 = *(const float4*)(Bp + (size_t)(k0 + 16 + bk1) * ldb + bc1);
        }
#pragma unroll
        for (int kk = 0; kk < 16; kk++) {
            float4 a0 = *(const float4*)&As[buf][kk][ty*8];
            float4 a1 = *(const float4*)&As[buf][kk][ty*8+4];
            ulonglong2 p0 = *(const ulonglong2*)&Bs[buf][kk][tx*8];
            ulonglong2 p1 = *(const ulonglong2*)&Bs[buf][kk][tx*8 + 4];
            unsigned long long b2[4] = {p0.x, p0.y, p1.x, p1.y};
            unsigned long long a2;
            a2 = dup2(a0.x);
#pragma unroll
            for (int j = 0; j < 4; j++) acc[0][j] = ffma2(a2, b2[j], acc[0][j]);
            a2 = dup2(a0.y);
#pragma unroll
            for (int j = 0; j < 4; j++) acc[1][j] = ffma2(a2, b2[j], acc[1][j]);
            a2 = dup2(a0.z);
#pragma unroll
            for (int j = 0; j < 4; j++) acc[2][j] = ffma2(a2, b2[j], acc[2][j]);
            a2 = dup2(a0.w);
#pragma unroll
            for (int j = 0; j < 4; j++) acc[3][j] = ffma2(a2, b2[j], acc[3][j]);
            a2 = dup2(a1.x);
#pragma unroll
            for (int j = 0; j < 4; j++) acc[4][j] = ffma2(a2, b2[j], acc[4][j]);
            a2 = dup2(a1.y);
#pragma unroll
            for (int j = 0; j < 4; j++) acc[5][j] = ffma2(a2, b2[j], acc[5][j]);
            a2 = dup2(a1.z);
#pragma unroll
            for (int j = 0; j < 4; j++) acc[6][j] = ffma2(a2, b2[j], acc[6][j]);
            a2 = dup2(a1.w);
#pragma unroll
            for (int j = 0; j < 4; j++) acc[7][j] = ffma2(a2, b2[j], acc[7][j]);
        }
        if (has_next) {
            const int nb = buf ^ 1;
            As[nb][ak0+0][ar0] = pa0.x; As[nb][ak0+1][ar0] = pa0.y;
            As[nb][ak0+2][ar0] = pa0.z; As[nb][ak0+3][ar0] = pa0.w;
            As[nb][ak1+0][ar1] = pa1.x; As[nb][ak1+1][ar1] = pa1.y;
            As[nb][ak1+2][ar1] = pa1.z; As[nb][ak1+3][ar1] = pa1.w;
            *(float4*)&Bs[nb][bk0][bc0] = pb0;
            *(float4*)&Bs[nb][bk1][bc1] = pb1;
            __syncthreads();
            buf = nb;
        }
    }

    const float bnf = rsqrtf(1.0f + LN_EPS);
    const int c0 = col0 + tx * 8;
    float bias8[8], sc8[8], sh8[8];
#pragma unroll
    for (int j = 0; j < 8; j++) bias8[j] = bias[c0 + j];
    if (HAS_BN) {
#pragma unroll
        for (int j = 0; j < 8; j++) { sc8[j] = scale[c0 + j] * bnf; sh8[j] = shift[c0 + j]; }
    }
#pragma unroll
    for (int i = 0; i < 8; i++) {
        const int r = row0 + ty * 8 + i;
        float out[8];
#pragma unroll
        for (int j = 0; j < 4; j++) unpack2(acc[i][j], out[2*j], out[2*j+1]);
#pragma unroll
        for (int j = 0; j < 8; j++) {
            float v = out[j] + bias8[j];
            if (HAS_BN) v = v * sc8[j] + sh8[j];
            if (RELU)   v = fmaxf(v, 0.f);
            out[j] = v;
        }
        if (HAS_RESID) {
            float4 r0 = *(const float4*)&resid[(size_t)r*ldc + c0];
            float4 r1 = *(const float4*)&resid[(size_t)r*ldc + c0 + 4];
            out[0]+=r0.x; out[1]+=r0.y; out[2]+=r0.z; out[3]+=r0.w;
            out[4]+=r1.x; out[5]+=r1.y; out[6]+=r1.z; out[7]+=r1.w;
        }
        *(float4*)&Cout[(size_t)r*ldc + c0]     = make_float4(out[0],out[1],out[2],out[3]);
        *(float4*)&Cout[(size_t)r*ldc + c0 + 4] = make_float4(out[4],out[5],out[6],out[7]);
    }
}

// ---------------- 64x128 tile variant, double-buffered (bit-identical arithmetic) ----------------
template<bool RELU, bool HAS_RESID, bool HAS_BN>
__global__ __launch_bounds__(128, 4)
void gemm64(const float* __restrict__ A, const float* __restrict__ Bm,
            const float* __restrict__ bias,
            const float* __restrict__ scale, const float* __restrict__ shift,
            const float* __restrict__ resid, float* __restrict__ Cout,
            int lda, int ldb, int ldc, int Kd)
{
    __shared__ float As[2][16][64];
    __shared__ float Bs[2][16][128];
    const int tid = threadIdx.x;
    const int tx = tid & 15, ty = tid >> 4;
    const int row0 = blockIdx.x * 64, col0 = blockIdx.y * 128;

    const int f0 = tid * 2, f1 = tid * 2 + 1;
    const int ar0 = f0 >> 2, ak0 = (f0 & 3) * 4;
    const int ar1 = f1 >> 2, ak1 = (f1 & 3) * 4;
    const int g0 = tid * 4;
    const int bk0 = g0 >> 5,       bc0 = (g0 & 31) * 4;
    const int bk1 = (g0+1) >> 5,   bc1 = ((g0+1) & 31) * 4;
    const int bk2 = (g0+2) >> 5,   bc2 = ((g0+2) & 31) * 4;
    const int bk3 = (g0+3) >> 5,   bc3 = ((g0+3) & 31) * 4;

    const float* Ar0 = A + (size_t)(row0 + ar0) * lda;
    const float* Ar1 = A + (size_t)(row0 + ar1) * lda;
    const float* Bp  = Bm + col0;

    unsigned long long acc[8][4];
#pragma unroll
    for (int i = 0; i < 8; i++)
#pragma unroll
        for (int j = 0; j < 4; j++) acc[i][j] = 0ull;

    float4 pa0 = *(const float4*)(Ar0 + ak0);
    float4 pa1 = *(const float4*)(Ar1 + ak1);
    float4 pb0 = *(const float4*)(Bp + (size_t)bk0 * ldb + bc0);
    float4 pb1 = *(const float4*)(Bp + (size_t)bk1 * ldb + bc1);
    float4 pb2 = *(const float4*)(Bp + (size_t)bk2 * ldb + bc2);
    float4 pb3 = *(const float4*)(Bp + (size_t)bk3 * ldb + bc3);
    As[0][ak0+0][ar0] = pa0.x; As[0][ak0+1][ar0] = pa0.y;
    As[0][ak0+2][ar0] = pa0.z; As[0][ak0+3][ar0] = pa0.w;
    As[0][ak1+0][ar1] = pa1.x; As[0][ak1+1][ar1] = pa1.y;
    As[0][ak1+2][ar1] = pa1.z; As[0][ak1+3][ar1] = pa1.w;
    *(float4*)&Bs[0][bk0][bc0] = pb0;
    *(float4*)&Bs[0][bk1][bc1] = pb1;
    *(float4*)&Bs[0][bk2][bc2] = pb2;
    *(float4*)&Bs[0][bk3][bc3] = pb3;
    __syncthreads();

    int buf = 0;
    for (int k0 = 0; k0 < Kd; k0 += 16) {
        const bool has_next = (k0 + 16 < Kd);
        if (has_next) {
            pa0 = *(const float4*)(Ar0 + k0 + 16 + ak0);
            pa1 = *(const float4*)(Ar1 + k0 + 16 + ak1);
            pb0 = *(const float4*)(Bp + (size_t)(k0 + 16 + bk0) * ldb + bc0);
            pb1 = *(const float4*)(Bp + (size_t)(k0 + 16 + bk1) * ldb + bc1);
            pb2 = *(const float4*)(Bp + (size_t)(k0 + 16 + bk2) * ldb + bc2);
            pb3 = *(const float4*)(Bp + (size_t)(k0 + 16 + bk3) * ldb + bc3);
        }
#pragma unroll
        for (int kk = 0; kk < 16; kk++) {
            float4 a0 = *(const float4*)&As[buf][kk][ty*8];
            float4 a1 = *(const float4*)&As[buf][kk][ty*8+4];
            ulonglong2 p0 = *(const ulonglong2*)&Bs[buf][kk][tx*8];
            ulonglong2 p1 = *(const ulonglong2*)&Bs[buf][kk][tx*8 + 4];
            unsigned long long b2[4] = {p0.x, p0.y, p1.x, p1.y};
            unsigned long long a2;
            a2 = dup2(a0.x);
#pragma unroll
            for (int j = 0; j < 4; j++) acc[0][j] = ffma2(a2, b2[j], acc[0][j]);
            a2 = dup2(a0.y);
#pragma unroll
            for (int j = 0; j < 4; j++) acc[1][j] = ffma2(a2, b2[j], acc[1][j]);
            a2 = dup2(a0.z);
#pragma unroll
            for (int j = 0; j < 4; j++) acc[2][j] = ffma2(a2, b2[j], acc[2][j]);
            a2 = dup2(a0.w);
#pragma unroll
            for (int j = 0; j < 4; j++) acc[3][j] = ffma2(a2, b2[j], acc[3][j]);
            a2 = dup2(a1.x);
#pragma unroll
            for (int j = 0; j < 4; j++) acc[4][j] = ffma2(a2, b2[j], acc[4][j]);
            a2 = dup2(a1.y);
#pragma unroll
            for (int j = 0; j < 4; j++) acc[5][j] = ffma2(a2, b2[j], acc[5][j]);
            a2 = dup2(a1.z);
#pragma unroll
            for (int j = 0; j < 4; j++) acc[6][j] = ffma2(a2, b2[j], acc[6][j]);
            a2 = dup2(a1.w);
#pragma unroll
            for (int j = 0; j < 4; j++) acc[7][j] = ffma2(a2, b2[j], acc[7][j]);
        }
        if (has_next) {
            const int nb = buf ^ 1;
            As[nb][ak0+0][ar0] = pa0.x; As[nb][ak0+1][ar0] = pa0.y;
            As[nb][ak0+2][ar0] = pa0.z; As[nb][ak0+3][ar0] = pa0.w;
            As[nb][ak1+0][ar1] = pa1.x; As[nb][ak1+1][ar1] = pa1.y;
            As[nb][ak1+2][ar1] = pa1.z; As[nb][ak1+3][ar1] = pa1.w;
            *(float4*)&Bs[nb][bk0][bc0] = pb0;
            *(float4*)&Bs[nb][bk1][bc1] = pb1;
            *(float4*)&Bs[nb][bk2][bc2] = pb2;
            *(float4*)&Bs[nb][bk3][bc3] = pb3;
            __syncthreads();
            buf = nb;
        }
    }

    const float bnf = rsqrtf(1.0f + LN_EPS);
    const int c0 = col0 + tx * 8;
    float bias8[8], sc8[8], sh8[8];
#pragma unroll
    for (int j = 0; j < 8; j++) bias8[j] = bias[c0 + j];
    if (HAS_BN) {
#pragma unroll
        for (int j = 0; j < 8; j++) { sc8[j] = scale[c0 + j] * bnf; sh8[j] = shift[c0 + j]; }
    }
#pragma unroll
    for (int i = 0; i < 8; i++) {
        const int r = row0 + ty * 8 + i;
        float out[8];
#pragma unroll
        for (int j = 0; j < 4; j++) unpack2(acc[i][j], out[2*j], out[2*j+1]);
#pragma unroll
        for (int j = 0; j < 8; j++) {
            float v = out[j] + bias8[j];
            if (HAS_BN) v = v * sc8[j] + sh8[j];
            if (RELU)   v = fmaxf(v, 0.f);
            out[j] = v;
        }
        if (HAS_RESID) {
            float4 r0 = *(const float4*)&resid[(size_t)r*ldc + c0];
            float4 r1 = *(const float4*)&resid[(size_t)r*ldc + c0 + 4];
            out[0]+=r0.x; out[1]+=r0.y; out[2]+=r0.z; out[3]+=r0.w;
            out[4]+=r1.x; out[5]+=r1.y; out[6]+=r1.z; out[7]+=r1.w;
        }
        *(float4*)&Cout[(size_t)r*ldc + c0]     = make_float4(out[0],out[1],out[2],out[3]);
        *(float4*)&Cout[(size_t)r*ldc + c0 + 4] = make_float4(out[4],out[5],out[6],out[7]);
    }
}

// ---------------- weight concat prep ----------------
__global__ void prep_kernel(const float* __restrict__ Ws, const float* __restrict__ Wn,
                            const float* __restrict__ bs)
{
    int idx = blockIdx.x * 256 + threadIdx.x;
    if (idx < NLAYERS * 256 * 512) {
        int i = idx / (256 * 512);
        int rem = idx % (256 * 512);
        int d = rem / 512, col = rem % 512;
        int h = col >> 7, e = col & 127;
        const float* src = (d < 128) ? Ws : Wn;
        d_WCAT[idx] = src[((((size_t)i * NHEADS) + h) * HD + (d & 127)) * HD + e];
    }
    if (idx < NLAYERS * 512) {
        int i = idx / 512, col = idx % 512;
        d_BSCAT[idx] = bs[(i * NHEADS + (col >> 7)) * HD + (col & 127)];
    }
}

// ---------------- KNN: 64 nodes x 4 j-partitions, j-loop unrolled x2 (bit-identical ADJ) ----------------
__global__ __launch_bounds__(256)
void knn_kernel(const float* __restrict__ C, int Ni, int W,
                unsigned long long* __restrict__ ADJ)
{
    __shared__ float2 sc[NMAX];
    __shared__ float sd[64 * 4 * KNN];
    __shared__ int   sj[64 * 4 * KNN];
    const int b = blockIdx.y;
    const int node0 = blockIdx.x * 64;
    const int t = threadIdx.x;
    const int nl = t & 63, part = t >> 6;
    const float2* cb = (const float2*)(C + (size_t)b * Ni * 2);
    for (int idx = t; idx < Ni; idx += 256) sc[idx] = cb[idx];
    __syncthreads();

    const int i = node0 + nl;
    const float2 me = sc[i];
    float bd[KNN]; int bj[KNN];
#pragma unroll
    for (int q = 0; q < KNN; q++) { bd[q] = 3.4e38f; bj[q] = 0x7fffffff; }

    auto try_insert = [&](float d2, int j) {
        if (d2 < bd[KNN-1]) {
#pragma unroll
            for (int q = KNN-1; q > 0; --q) {
                bool prev = d2 < bd[q-1];
                bool here = d2 < bd[q];
                float nb = prev ? bd[q-1] : (here ? d2 : bd[q]);
                int   nj = prev ? bj[q-1] : (here ? j  : bj[q]);
                bd[q] = nb; bj[q] = nj;
            }
            if (d2 < bd[0]) { bd[0] = d2; bj[0] = j; }
        }
    };

    const int jlen = Ni >> 2;
    const int j0 = part * jlen;
    for (int jj = 0; jj < jlen; jj += 2) {
        int j = j0 + jj;
        float4 p = *(const float4*)(&sc[j]);
        float dx0 = me.x - p.x, dy0 = me.y - p.y;
        float d20 = dx0 * dx0 + dy0 * dy0;
        float dx1 = me.x - p.z, dy1 = me.y - p.w;
        float d21 = dx1 * dx1 + dy1 * dy1;
        try_insert(d20, j);
        try_insert(d21, j + 1);
    }
#pragma unroll
    for (int q = 0; q < KNN; q++) {
        sd[(nl * 4 + part) * KNN + q] = bd[q];
        sj[(nl * 4 + part) * KNN + q] = bj[q];
    }
    __syncthreads();

    if (t < 64) {
        float md[KNN]; int mj[KNN];
#pragma unroll
        for (int q = 0; q < KNN; q++) { md[q] = 3.4e38f; mj[q] = 0x7fffffff; }
        for (int p = 0; p < 4; p++) {
#pragma unroll
            for (int q = 0; q < KNN; q++) {
                float d2 = sd[(t * 4 + p) * KNN + q];
                int   j  = sj[(t * 4 + p) * KNN + q];
                if (d2 < md[KNN-1]) {
#pragma unroll
                    for (int w = KNN-1; w > 0; --w) {
                        bool prev = d2 < md[w-1];
                        bool here = d2 < md[w];
                        float nb = prev ? md[w-1] : (here ? d2 : md[w]);
                        int   nj = prev ? mj[w-1] : (here ? j  : mj[w]);
                        md[w] = nb; mj[w] = nj;
                    }
                    if (d2 < md[0]) { md[0] = d2; mj[0] = j; }
                }
            }
        }
        const int gi = node0 + t;
        const size_t rowbase = ((size_t)b * Ni + gi) * W;
#pragma unroll
        for (int q = 0; q < KNN; q++) {
            int j = mj[q];
            atomicOr(&ADJ[rowbase + (j >> 6)], 1ull << (j & 63));
            atomicOr(&ADJ[((size_t)b * Ni + j) * W + (gi >> 6)], 1ull << (gi & 63));
        }
    }
}

// ---------------- LayerNorm: 4 nodes per 512-thread block ----------------
__global__ __launch_bounds__(512)
void ln_kernel(const float* __restrict__ X, const float* __restrict__ gg,
               const float* __restrict__ bb, float* __restrict__ out, int ldo)
{
    __shared__ float sh[16];
    const size_t node = (size_t)blockIdx.x * 4 + (threadIdx.x >> 7);
    const int t = threadIdx.x & 127;
    const int nslot = (threadIdx.x >> 7) * 4;
    float v = X[node*HD + t];
    float s = v;
#pragma unroll
    for (int o = 16; o > 0; o >>= 1) s += __shfl_xor_sync(0xffffffffu, s, o);
    if ((t & 31) == 0) sh[nslot + (t >> 5)] = s;
    __syncthreads();
    float mean = (sh[nslot]+sh[nslot+1]+sh[nslot+2]+sh[nslot+3]) * (1.f/HD);
    __syncthreads();
    float dd = v - mean;
    float q = dd*dd;
#pragma unroll
    for (int o = 16; o > 0; o >>= 1) q += __shfl_xor_sync(0xffffffffu, q, o);
    if ((t & 31) == 0) sh[nslot + (t >> 5)] = q;
    __syncthreads();
    float var = (sh[nslot]+sh[nslot+1]+sh[nslot+2]+sh[nslot+3]) * (1.f/HD);
    out[node*(size_t)ldo + t] = dd * rsqrtf(var + LN_EPS) * gg[t] + bb[t];
}

// ---------------- fused neighbor-mean aggregation + degree ----------------
__global__ __launch_bounds__(128)
void agg_kernel(float* __restrict__ XM, const unsigned long long* __restrict__ ADJ,
                float* __restrict__ DINV, int Ni, int W)
{
    const int g = blockIdx.x;
    const int t = threadIdx.x;
    const int b = g / Ni;
    const size_t base = (size_t)b*Ni;
    const unsigned long long* row = ADJ + (size_t)g*W;
    float acc = 0.f;
    int dcnt = 0;
    for (int w = 0; w < W; w++) {
        unsigned long long word = row[w];
        dcnt += __popcll(word);
        while (word) {
            int bit = __ffsll((long long)word) - 1;
            word &= word - 1;
            int j = w*64 + bit;
            acc += XM[(base + j)*2*HD + t];
        }
    }
    float fd = (float)dcnt;
    XM[(size_t)g*2*HD + HD + t] = acc * (1.0f / fd);
    if (t == 0) DINV[g] = rsqrtf(fd);
}

// ---------------- Y = x @ Wq ----------------
__global__ void yq_kernel(const float* __restrict__ X, const float* __restrict__ Wq,
                          float* __restrict__ Y, int total)
{
    int g = blockIdx.x*8 + threadIdx.y;
    if (g >= total) return;
    int lane = threadIdx.x;
    float4 xv = *(const float4*)&X[(size_t)g*HD + lane*4];
    float4 wv = *(const float4*)&Wq[lane*4];
    float a = xv.x*wv.x + xv.y*wv.y + xv.z*wv.z + xv.w*wv.w;
#pragma unroll
    for (int o = 16; o > 0; o >>= 1) a += __shfl_xor_sync(0xffffffffu, a, o);
    if (lane == 0) Y[g] = a;
}

// ---------------- SAGPool score ----------------
__global__ void score_kernel(const unsigned long long* __restrict__ ADJ, int W, int Ni, int total,
                             const float* __restrict__ DINV, const float* __restrict__ Y,
                             const float* __restrict__ bqp, float* __restrict__ S)
{
    int g = blockIdx.x*256 + threadIdx.x;
    if (g >= total) return;
    int b = g / Ni;
    size_t base = (size_t)b*Ni;
    const unsigned long long* row = ADJ + (size_t)g*W;
    float acc = 0.f;
    for (int w = 0; w < W; w++) {
        unsigned long long word = row[w];
        while (word) {
            int bit = __ffsll((long long)word) - 1;
            word &= word - 1;
            int j = w*64 + bit;
            acc += DINV[base + j] * Y[base + j];
        }
    }
    S[g] = DINV[g] * acc + bqp[0];
}

// ---------------- bitonic top-k ----------------
__global__ __launch_bounds__(1024)
void topk_kernel(const float* __restrict__ S, int Ni, int kk,
                 int* __restrict__ TOPI, float* __restrict__ TOPV)
{
    __shared__ float sv[NMAX];
    __shared__ int   si[NMAX];
    const int b = blockIdx.x;
    const int tid = threadIdx.x;
    for (int i = tid; i < Ni; i += 1024) { sv[i] = S[(size_t)b*Ni + i]; si[i] = i; }
    __syncthreads();
    for (int k = 2; k <= Ni; k <<= 1) {
        for (int j = k >> 1; j > 0; j >>= 1) {
            for (int i = tid; i < Ni; i += 1024) {
                int l = i ^ j;
                if (l > i) {
                    bool up = ((i & k) == 0);
                    float vi = sv[i], vl = sv[l];
                    int ii = si[i], il = si[l];
                    bool iAfterL = (vi < vl) || (vi == vl && ii > il);
                    bool dosw = up ? iAfterL : !iAfterL;
                    if (dosw) { sv[i] = vl; sv[l] = vi; si[i] = il; si[l] = ii; }
                }
            }
            __syncthreads();
        }
    }
    for (int r = tid; r < kk; r += 1024) {
        TOPI[(size_t)b*kk + r] = si[r];
        TOPV[(size_t)b*kk + r] = sv[r];
    }
}

// ---------------- gather + tanh gate + (optional) next-layer ln1 into XM ----------------
__global__ __launch_bounds__(128)
void gather_kernel(const float* __restrict__ Xo, const float* __restrict__ Co,
                   float* __restrict__ Xn, float* __restrict__ Cn,
                   const int* __restrict__ TOPI, const float* __restrict__ TOPV,
                   int Ni, int kk,
                   const float* __restrict__ lng, const float* __restrict__ lnb,
                   float* __restrict__ lnout)
{
    __shared__ float sh[4];
    const int b = blockIdx.y, r = blockIdx.x, t = threadIdx.x;
    const int src = TOPI[(size_t)b*kk + r];
    const float gte = tanhf(TOPV[(size_t)b*kk + r]);
    const size_t node = (size_t)b*kk + r;
    float v = Xo[((size_t)b*Ni + src)*HD + t] * gte;
    Xn[node*HD + t] = v;
    if (t < 2) Cn[node*2 + t] = Co[((size_t)b*Ni + src)*2 + t];

    if (lng) {
        float s = v;
#pragma unroll
        for (int o = 16; o > 0; o >>= 1) s += __shfl_xor_sync(0xffffffffu, s, o);
        if ((t & 31) == 0) sh[t >> 5] = s;
        __syncthreads();
        float mean = (sh[0]+sh[1]+sh[2]+sh[3]) * (1.f/HD);
        __syncthreads();
        float dd = v - mean;
        float q = dd*dd;
#pragma unroll
        for (int o = 16; o > 0; o >>= 1) q += __shfl_xor_sync(0xffffffffu, q, o);
        if ((t & 31) == 0) sh[t >> 5] = q;
        __syncthreads();
        float var = (sh[0]+sh[1]+sh[2]+sh[3]) * (1.f/HD);
        lnout[node*(size_t)(2*HD) + t] = dd * rsqrtf(var + LN_EPS) * lng[t] + lnb[t];
    }
}

// ---------------- two-phase readout ----------------
__global__ __launch_bounds__(128)
void readout_part(const float* __restrict__ Xp, int kk, float* __restrict__ RPART)
{
    const int c = blockIdx.x;
    const int b = blockIdx.y;
    const int t = threadIdx.x;
    const int rows = kk >> 3;
    const int r0 = c * rows;
    float mx = -3.4e38f, sm = 0.f;
    for (int r = 0; r < rows; r++) {
        float v = Xp[((size_t)b*kk + r0 + r)*HD + t];
        mx = fmaxf(mx, v);
        sm += v;
    }
    RPART[((size_t)b*8 + c)*2*HD + t]      = mx;
    RPART[((size_t)b*8 + c)*2*HD + HD + t] = sm;
}

__global__ __launch_bounds__(128)
void readout_comb(const float* __restrict__ RPART, int kk, float* __restrict__ PICKS)
{
    const int b = blockIdx.x, t = threadIdx.x;
    float mx = -3.4e38f, sm = 0.f;
#pragma unroll
    for (int c = 0; c < 8; c++) {
        mx = fmaxf(mx, RPART[((size_t)b*8 + c)*2*HD + t]);
        sm += RPART[((size_t)b*8 + c)*2*HD + HD + t];
    }
    PICKS[b*2*HD + t]      += mx;
    PICKS[b*2*HD + HD + t] += sm / (float)kk;
}

// ---------------- final MLP ----------------
__global__ __launch_bounds__(256)
void final_kernel(const float* __restrict__ Wf1, const float* __restrict__ bf1,
                  const float* __restrict__ Wf2, const float* __restrict__ bf2,
                  float* __restrict__ out)
{
    __shared__ float f1s[BB*HD];
    const int tid = threadIdx.x;
    for (int o = tid; o < BB*HD; o += 256) {
        int b = o >> 7, c = o & 127;
        float a = bf1[c];
        const float* pr = &d_PICKS[b*2*HD];
        for (int k = 0; k < 2*HD; k++) a += pr[k] * Wf1[k*HD + c];
        f1s[o] = fmaxf(a, 0.f);
    }
    __syncthreads();
    int b = tid >> 5, c = tid & 31;
    float a = bf2[c];
    for (int k = 0; k < HD; k++) a += f1s[b*HD + k] * Wf2[k*32 + c];
    out[b*32 + c] = fmaxf(a, 0.f);
}

// ---------------- host orchestration ----------------
#define GEMM_CALL(R, RS, BN, M, NB, Aa, Bb, bi, sc, sh, re, Co, la, lb, lc, Kd)          \
    do {                                                                                  \
        if ((M) >= 12288)                                                                 \
            gemm128<R,RS,BN><<<dim3((M)/128, (NB)), 256>>>(Aa, Bb, bi, sc, sh, re, Co,    \
                                                           la, lb, lc, Kd);               \
        else                                                                              \
            gemm64<R,RS,BN><<<dim3((M)/64, (NB)), 128>>>(Aa, Bb, bi, sc, sh, re, Co,      \
                                                         la, lb, lc, Kd);                 \
    } while (0)

extern "C" void kernel_launch(void* const* d_in, const int* in_sizes, int n_in,
                              void* d_out, int out_size)
{
    const float* feats = (const float*)d_in[0];
    const float* cent  = (const float*)d_in[1];
    const float* Wp1   = (const float*)d_in[2];
    const float* bp1   = (const float*)d_in[3];
    const float* bn_g  = (const float*)d_in[4];
    const float* bn_b  = (const float*)d_in[5];
    const float* Wp2   = (const float*)d_in[6];
    const float* bp2   = (const float*)d_in[7];
    const float* g1    = (const float*)d_in[8];
    const float* be1   = (const float*)d_in[9];
    const float* g2    = (const float*)d_in[10];
    const float* be2   = (const float*)d_in[11];
    const float* Ws    = (const float*)d_in[12];
    const float* Wn    = (const float*)d_in[13];
    const float* bs    = (const float*)d_in[14];
    const float* Wg    = (const float*)d_in[15];
    const float* bg    = (const float*)d_in[16];
    const float* W1    = (const float*)d_in[17];
    const float* b1    = (const float*)d_in[18];
    const float* W2    = (const float*)d_in[19];
    const float* b2    = (const float*)d_in[20];
    const float* Wq    = (const float*)d_in[21];
    const float* bq    = (const float*)d_in[22];
    const float* Wf1   = (const float*)d_in[23];
    const float* bf1   = (const float*)d_in[24];
    const float* Wf2   = (const float*)d_in[25];
    const float* bf2   = (const float*)d_in[26];

    float *Xa, *Xb, *XM, *XN, *T1, *Hb, *Ca, *Cb, *DINV, *Y, *S, *TOPV, *PICKS, *RPART;
    float *WCAT, *BSCAT;
    int* TOPI;
    unsigned long long* ADJ;
    cudaGetSymbolAddress((void**)&Xa, d_X);
    cudaGetSymbolAddress((void**)&Xb, d_XG);
    cudaGetSymbolAddress((void**)&XM, d_XM);
    cudaGetSymbolAddress((void**)&XN, d_XN);
    cudaGetSymbolAddress((void**)&T1, d_T1);
    cudaGetSymbolAddress((void**)&Hb, d_H);
    cudaGetSymbolAddress((void**)&Ca, d_C);
    cudaGetSymbolAddress((void**)&Cb, d_CG);
    cudaGetSymbolAddress((void**)&WCAT, d_WCAT);
    cudaGetSymbolAddress((void**)&BSCAT, d_BSCAT);
    cudaGetSymbolAddress((void**)&ADJ, d_ADJ);
    cudaGetSymbolAddress((void**)&DINV, d_DINV);
    cudaGetSymbolAddress((void**)&Y,  d_Y);
    cudaGetSymbolAddress((void**)&S,  d_S);
    cudaGetSymbolAddress((void**)&TOPI, d_TOPI);
    cudaGetSymbolAddress((void**)&TOPV, d_TOPV);
    cudaGetSymbolAddress((void**)&PICKS, d_PICKS);
    cudaGetSymbolAddress((void**)&RPART, d_RPART);

    const int M0 = MAXNODES;   // 16384 rows

    // weight concat prep
    prep_kernel<<<(NLAYERS*256*512 + 255)/256, 256>>>(Ws, Wn, bs);

    // preconv: T1 = relu(bn(feats@Wp1+bp1)); X = T1@Wp2 + bp2
    GEMM_CALL(true, false, true, M0, 1,
              feats, Wp1, bp1, bn_g, bn_b, nullptr, T1, 512, 128, 128, 512);
    GEMM_CALL(false, false, false, M0, 1,
              T1, Wp2, bp2, nullptr, nullptr, nullptr, Xa, 128, 128, 128, 128);

    cudaMemcpyAsync(Ca, cent, (size_t)M0*2*sizeof(float), cudaMemcpyDeviceToDevice);
    cudaMemsetAsync(PICKS, 0, BB*2*HD*sizeof(float));

    // layer-0 ln1 -> XM[:, :128]
    ln_kernel<<<M0/4, 512>>>(Xa, g1, be1, XM, 2*HD);

    float *Xcur = Xa, *Xnext = Xb, *Ccur = Ca, *Cnext = Cb;
    int Ni = NMAX;
    for (int i = 0; i < NLAYERS; i++) {
        const int W = Ni / 64;
        const int total = BB * Ni;
        const int kk = Ni / 2;

        cudaMemsetAsync(ADJ, 0, (size_t)total * W * sizeof(unsigned long long));
        knn_kernel<<<dim3(Ni/64, BB), 256>>>(Ccur, Ni, W, ADJ);

        // fused agg + degree (XM[:, :128] holds ln1 already)
        agg_kernel<<<total, 128>>>(XM, ADJ, DINV, Ni, W);

        // fused 4-head GEMM: Hb = relu([XN|Mg] @ WCAT + BSCAT)   [total x 512]
        GEMM_CALL(true, false, false, total, 4,
                  XM, WCAT + (size_t)i*256*512, BSCAT + (size_t)i*512,
                  nullptr, nullptr, nullptr, Hb, 256, 512, 512, 256);
        // out-proj + residual: X += Hb @ Wg + bg
        GEMM_CALL(false, true, false, total, 1,
                  Hb, Wg + (size_t)i*NHEADS*HD*HD, bg + i*HD,
                  nullptr, nullptr, Xcur, Xcur, 512, 128, 128, 512);

        // FFN
        ln_kernel<<<total/4, 512>>>(Xcur, g2 + i*HD, be2 + i*HD, XN, HD);
        GEMM_CALL(true, false, false, total, 1,
                  XN, W1 + (size_t)i*HD*HD, b1 + i*HD,
                  nullptr, nullptr, nullptr, T1, 128, 128, 128, 128);
        GEMM_CALL(false, true, false, total, 1,
                  T1, W2 + (size_t)i*HD*HD, b2 + i*HD,
                  nullptr, nullptr, Xcur, Xcur, 128, 128, 128, 128);

        // SAGPool
        yq_kernel<<<(total+7)/8, dim3(32, 8)>>>(Xcur, Wq + (size_t)i*HD, Y, total);
        score_kernel<<<(total+255)/256, 256>>>(ADJ, W, Ni, total, DINV, Y, bq + i, S);
        topk_kernel<<<BB, 1024>>>(S, Ni, kk, TOPI, TOPV);
        if (i + 1 < NLAYERS)
            gather_kernel<<<dim3(kk, BB), 128>>>(Xcur, Ccur, Xnext, Cnext, TOPI, TOPV,
                                                 Ni, kk, g1 + (i+1)*HD, be1 + (i+1)*HD, XM);
        else
            gather_kernel<<<dim3(kk, BB), 128>>>(Xcur, Ccur, Xnext, Cnext, TOPI, TOPV,
                                                 Ni, kk, nullptr, nullptr, nullptr);
        readout_part<<<dim3(8, BB), 128>>>(Xnext, kk, RPART);
        readout_comb<<<BB, 128>>>(RPART, kk, PICKS);

        // ping-pong
        float* t;
        t = Xcur; Xcur = Xnext; Xnext = t;
        t = Ccur; Ccur = Cnext; Cnext = t;
        Ni = kk;
    }

    final_kernel<<<1, 256>>>(Wf1, bf1, Wf2, bf2, (float*)d_out);
}